// round 9
// baseline (speedup 1.0000x reference)
#include <cuda_runtime.h>
#include <cuda_bf16.h>
#include <math.h>
#include <stdint.h>

// Problem dims (fixed)
#define Bq   2
#define Sq   2048
#define Dq   1024
#define Hq   8
#define FFNq 4096
#define DKq  128
#define VDq  2048
#define DVq  256
#define Mq   (Bq*Sq)        // 4096 rows
#define NCAT 6144           // Q(1024) | K(1024) | V(2048) | G(2048)
#define EPSq 1e-5f

// ---------------- scratch (device globals; no allocations allowed) ----------------
__device__ float g_Wcat [(size_t)Dq*NCAT];            // packed [Wq|Wk|Wv|Wg] (D x NCAT)
__device__ float g_QKVG[(size_t)Mq*NCAT];
__device__ float g_Y  [(size_t)Mq*VDq];               // retention out (fp32)
__device__ float g_X2 [(size_t)Mq*Dq];
__device__ float g_cq[Sq*64], g_sq[Sq*64], g_ck[Sq*64], g_sk[Sq*64];

// hi/lo bf16 split operands for tensor-core GEMMs
__device__ __nv_bfloat16 g_XnH [(size_t)Mq*Dq],    g_XnL [(size_t)Mq*Dq];
__device__ __nv_bfloat16 g_WcTH[(size_t)NCAT*Dq],  g_WcTL[(size_t)NCAT*Dq];
__device__ __nv_bfloat16 g_WOTH[(size_t)Dq*VDq],   g_WOTL[(size_t)Dq*VDq];
__device__ __nv_bfloat16 g_W1TH[(size_t)FFNq*Dq],  g_W1TL[(size_t)FFNq*Dq];
__device__ __nv_bfloat16 g_W2TH[(size_t)Dq*FFNq],  g_W2TL[(size_t)Dq*FFNq];
__device__ __nv_bfloat16 g_YH  [(size_t)Mq*VDq],   g_YL  [(size_t)Mq*VDq];
__device__ __nv_bfloat16 g_HnH [(size_t)Mq*Dq],    g_HnL [(size_t)Mq*Dq];
__device__ __nv_bfloat16 g_FfH [(size_t)Mq*FFNq],  g_FfL [(size_t)Mq*FFNq];

// retention operands: decay-folded Q/K and V, hi/lo bf16, (b,h,s,*) layout
__device__ __nv_bfloat16 g_QrH[(size_t)Bq*Hq*Sq*DKq], g_QrL[(size_t)Bq*Hq*Sq*DKq];
__device__ __nv_bfloat16 g_KrH[(size_t)Bq*Hq*Sq*DKq], g_KrL[(size_t)Bq*Hq*Sq*DKq];
__device__ __nv_bfloat16 g_VrH[(size_t)Bq*Hq*Sq*DVq], g_VrL[(size_t)Bq*Hq*Sq*DVq];

// ---------------- helpers ----------------
__device__ __forceinline__ uint32_t s2u(const void* p) {
    uint32_t a;
    asm("{ .reg .u64 t; cvta.to.shared.u64 t, %1; cvt.u32.u64 %0, t; }" : "=r"(a) : "l"(p));
    return a;
}
__device__ __forceinline__ void split2(float v, __nv_bfloat16& h, __nv_bfloat16& l) {
    h = __float2bfloat16_rn(v);
    l = __float2bfloat16_rn(v - __bfloat162float(h));
}

#define LDSM4(r, addr) \
    asm volatile("ldmatrix.sync.aligned.m8n8.x4.shared.b16 {%0,%1,%2,%3}, [%4];" \
        : "=r"((r)[0]), "=r"((r)[1]), "=r"((r)[2]), "=r"((r)[3]) : "r"(addr))
#define LDSM4T(r, addr) \
    asm volatile("ldmatrix.sync.aligned.m8n8.x4.trans.shared.b16 {%0,%1,%2,%3}, [%4];" \
        : "=r"((r)[0]), "=r"((r)[1]), "=r"((r)[2]), "=r"((r)[3]) : "r"(addr))

#define MMA16816(d, a, b0v, b1v) \
    asm volatile("mma.sync.aligned.m16n8k16.row.col.f32.bf16.bf16.f32 " \
        "{%0,%1,%2,%3},{%4,%5,%6,%7},{%8,%9},{%0,%1,%2,%3};" \
        : "+f"((d)[0]), "+f"((d)[1]), "+f"((d)[2]), "+f"((d)[3]) \
        : "r"((a)[0]), "r"((a)[1]), "r"((a)[2]), "r"((a)[3]), "r"(b0v), "r"(b1v))

#define CP_ASYNC16(dst, src) \
    asm volatile("cp.async.cg.shared.global [%0], [%1], 16;" :: "r"(dst), "l"(src) : "memory")
#define CP_COMMIT() asm volatile("cp.async.commit_group;" ::: "memory")
#define CP_WAIT(n)  asm volatile("cp.async.wait_group %0;" :: "n"(n) : "memory")

// ---------------- weight repack: (H,D,DK)/(H,D,DV) -> plain (D, NCAT) ----------------
__global__ void repack_k(const float* __restrict__ Wq, const float* __restrict__ Wk,
                         const float* __restrict__ Wv, const float* __restrict__ Wg) {
    int idx = blockIdx.x * blockDim.x + threadIdx.x;
    if (idx >= Dq * NCAT) return;
    int d = idx / NCAT, n = idx % NCAT;
    float v;
    if (n < 1024)      { int h = n >> 7, k = n & 127;            v = Wq[((size_t)h*Dq + d)*DKq + k]; }
    else if (n < 2048) { int nn = n-1024; int h = nn>>7, k = nn&127; v = Wk[((size_t)h*Dq + d)*DKq + k]; }
    else if (n < 4096) { int nn = n-2048; int h = nn>>8, vv = nn&255; v = Wv[((size_t)h*Dq + d)*DVq + vv]; }
    else               { v = Wg[(size_t)d*VDq + (n-4096)]; }
    g_Wcat[idx] = v;
}

// ---------------- tiled transpose + hi/lo split ----------------
__global__ __launch_bounds__(256) void transpose_split_k(const float* __restrict__ src,
                                                         __nv_bfloat16* __restrict__ dH,
                                                         __nv_bfloat16* __restrict__ dL,
                                                         int R, int C) {
    __shared__ float t[32][33];
    int c0 = blockIdx.x * 32, r0 = blockIdx.y * 32;
    int x = threadIdx.x & 31, y = threadIdx.x >> 5;
    #pragma unroll
    for (int i = 0; i < 32; i += 8) t[y+i][x] = src[(size_t)(r0 + y + i)*C + c0 + x];
    __syncthreads();
    #pragma unroll
    for (int i = 0; i < 32; i += 8) {
        float v = t[x][y+i];
        size_t o = (size_t)(c0 + y + i)*R + r0 + x;
        __nv_bfloat16 h, l; split2(v, h, l);
        dH[o] = h; dL[o] = l;
    }
}

// ---------------- xpos tables ----------------
__global__ void xpos_tables_k() {
    int idx = blockIdx.x * blockDim.x + threadIdx.x;
    if (idx >= Sq*64) return;
    int pos = idx >> 6, i = idx & 63;
    float sv    = (2.0f*i + 0.4f*DKq) / (1.4f*DKq);
    float scale = powf(sv, (float)pos / 512.0f);
    float invf  = powf(10000.0f, -((float)i) / 64.0f);
    float ang   = (float)pos * invf;
    float s, c; sincosf(ang, &s, &c);
    g_cq[idx] = c*scale;  g_sq[idx] = s*scale;
    g_ck[idx] = c/scale;  g_sk[idx] = s/scale;
}

// ---------------- layernorm (rows of 1024) -> hi/lo bf16 ----------------
__global__ __launch_bounds__(256) void layernorm_split_k(const float* __restrict__ x,
                                                         const float* __restrict__ w,
                                                         const float* __restrict__ b,
                                                         __nv_bfloat16* __restrict__ yH,
                                                         __nv_bfloat16* __restrict__ yL) {
    int row = blockIdx.x;
    const float* xr = x + (size_t)row * Dq;
    float v[4]; float s = 0.f;
    #pragma unroll
    for (int i = 0; i < 4; i++) { v[i] = xr[threadIdx.x + i*256]; s += v[i]; }
    __shared__ float red[8];
    #pragma unroll
    for (int o = 16; o > 0; o >>= 1) s += __shfl_xor_sync(~0u, s, o);
    if ((threadIdx.x & 31) == 0) red[threadIdx.x >> 5] = s;
    __syncthreads();
    float mu = 0.f;
    #pragma unroll
    for (int i = 0; i < 8; i++) mu += red[i];
    mu *= (1.0f/Dq);
    __syncthreads();
    float vs = 0.f;
    #pragma unroll
    for (int i = 0; i < 4; i++) { float d = v[i]-mu; vs += d*d; }
    #pragma unroll
    for (int o = 16; o > 0; o >>= 1) vs += __shfl_xor_sync(~0u, vs, o);
    if ((threadIdx.x & 31) == 0) red[threadIdx.x >> 5] = vs;
    __syncthreads();
    float var = 0.f;
    #pragma unroll
    for (int i = 0; i < 8; i++) var += red[i];
    var *= (1.0f/Dq);
    float rstd = rsqrtf(var + EPSq);
    #pragma unroll
    for (int i = 0; i < 4; i++) {
        int c = threadIdx.x + i*256;
        float o = (v[i]-mu)*rstd*w[c] + b[c];
        __nv_bfloat16 h, l; split2(o, h, l);
        yH[(size_t)row*Dq + c] = h;
        yL[(size_t)row*Dq + c] = l;
    }
}

// ---------------- xpos apply + decay fold + hi/lo split ----------------
// Q row scaled by gamma^(s&63), K row scaled by gamma^(-(s&63))
__global__ void xpos_apply_k() {
    int idx = blockIdx.x * blockDim.x + threadIdx.x;
    if (idx >= Bq*Sq*Hq*64) return;
    int i = idx & 63, h = (idx >> 6) & 7, s = (idx >> 9) & (Sq-1), b = idx >> 20;
    int row = b*Sq + s;
    const float* qr = g_QKVG + (size_t)row * NCAT;
    int ti = s*64 + i;
    size_t ob = ((size_t)(b*Hq + h)*Sq + s)*DKq + 2*i;

    double lg = log(1.0/32.0) + (double)h * ((log(1.0/512.0) - log(1.0/32.0)) / 7.0);
    float gamma = 1.0f - (float)exp(lg);
    float l2g = log2f(gamma);
    int nl = s & 63;
    float qsc = exp2f((float)nl * l2g);     // <= 1
    float ksc = exp2f(-(float)nl * l2g);    // <= gamma^-63 ~ 7.4

    {
        float q0 = qr[h*128 + 2*i], q1 = qr[h*128 + 2*i + 1];
        float c = g_cq[ti], sn = g_sq[ti];
        float r0 = (q0*c - q1*sn) * qsc;
        float r1 = (q1*c + q0*sn) * qsc;
        __nv_bfloat16 h0, l0, h1, l1;
        split2(r0, h0, l0); split2(r1, h1, l1);
        g_QrH[ob] = h0; g_QrH[ob+1] = h1;
        g_QrL[ob] = l0; g_QrL[ob+1] = l1;
    }
    {
        float k0 = qr[1024 + h*128 + 2*i], k1 = qr[1024 + h*128 + 2*i + 1];
        float c = g_ck[ti], sn = g_sk[ti];
        float r0 = (k0*c - k1*sn) * ksc;
        float r1 = (k1*c + k0*sn) * ksc;
        __nv_bfloat16 h0, l0, h1, l1;
        split2(r0, h0, l0); split2(r1, h1, l1);
        g_KrH[ob] = h0; g_KrH[ob+1] = h1;
        g_KrL[ob] = l0; g_KrL[ob+1] = l1;
    }
}

// ---------------- V split: QKVG V-part -> (b,h,s,v) hi/lo bf16 ----------------
__global__ void vsplit_k() {
    int idx = blockIdx.x * blockDim.x + threadIdx.x;   // Bq*Sq*VDq / 2 (2 elems per thread)
    if (idx >= Bq*Sq*VDq/2) return;
    int e2 = idx * 2;
    int v = e2 & (VDq-1);
    int row = e2 >> 11;                   // b*Sq + s
    int h = v >> 8, vv = v & 255;
    const float* src = g_QKVG + (size_t)row*NCAT + 2048 + v;
    int b = row >> 11, s = row & (Sq-1);
    size_t ob = ((size_t)(b*Hq + h)*Sq + s)*DVq + vv;
    float a0 = src[0], a1 = src[1];
    __nv_bfloat16 h0, l0, h1, l1;
    split2(a0, h0, l0); split2(a1, h1, l1);
    *(__nv_bfloat162*)(g_VrH + ob) = __nv_bfloat162(h0, h1);
    *(__nv_bfloat162*)(g_VrL + ob) = __nv_bfloat162(l0, l1);
}

// =====================================================================
// retention on HMMA: per CTA (b, h, 64-query tile)
// phase 1: S = QK^T (3-term bf16 split), fp32 rescale by gamma^(s0-t0),
//          diag mask, split to hi/lo in SMEM
// phase 2: Y += S V (3-term), Y fp32 in registers
// decay folded into Q/K at xpos time; tile skip when factor < 2^-40.
// =====================================================================
#define RSTRQ 272   // (128+8) bf16 * 2B
#define RSTRV 528   // (256+8) bf16 * 2B
#define RSTRS 144   // (64+8)  bf16 * 2B
#define ROFF_QH 0
#define ROFF_QL 17408
#define ROFF_KH 34816
#define ROFF_KL 52224
#define ROFF_VH 69632
#define ROFF_VL 103424
#define ROFF_SH 137216
#define ROFF_SL 146432
#define RET_SMEM 155648

__global__ __launch_bounds__(256) void retention_t_k() {
    extern __shared__ char smc[];
    const uint32_t sb = s2u(smc);
    const int tid = threadIdx.x, lane = tid & 31, warp = tid >> 5;
    const int qt = 31 - blockIdx.x, h = blockIdx.y, b = blockIdx.z;
    const int s0 = qt * 64;

    double lg = log(1.0/32.0) + (double)h * ((log(1.0/512.0) - log(1.0/32.0)) / 7.0);
    float gamma = 1.0f - (float)exp(lg);
    float l2g = log2f(gamma);
    float nl2g = -l2g;

    const size_t bh = (size_t)(b*Hq + h);
    const char* Qh = (const char*)(g_QrH + (bh*Sq + s0)*DKq);
    const char* Ql = (const char*)(g_QrL + (bh*Sq + s0)*DKq);

    // load Q tile once (64 x 128 bf16 hi/lo)
    {
        int row = tid >> 2, q4 = tid & 3;
        #pragma unroll
        for (int c = q4; c < 16; c += 4) {
            CP_ASYNC16(sb + ROFF_QH + row*RSTRQ + c*16, Qh + row*256 + c*16);
            CP_ASYNC16(sb + ROFF_QL + row*RSTRQ + c*16, Ql + row*256 + c*16);
        }
        CP_COMMIT();
    }

    // decay-truncation start tile
    int kt0 = 0;
    {
        float ktf = ((float)s0 - 63.0f - 40.0f/nl2g) * (1.0f/64.0f);
        if (ktf > 0.0f) kt0 = (int)ceilf(ktf);
        if (kt0 > qt) kt0 = qt;
        if (kt0 < 0) kt0 = 0;
    }

    const int wm = (warp >> 2) * 32;      // query rows (both phases)
    const int wn1 = (warp & 3) * 16;      // phase1 key cols
    const int wn2 = (warp & 3) * 64;      // phase2 vd cols

    float accY[2][8][4];
    #pragma unroll
    for (int a = 0; a < 2; a++)
        #pragma unroll
        for (int n = 0; n < 8; n++)
            #pragma unroll
            for (int e = 0; e < 4; e++) accY[a][n][e] = 0.f;

    const char* KhB = (const char*)(g_KrH + bh*Sq*DKq);
    const char* KlB = (const char*)(g_KrL + bh*Sq*DKq);
    const char* VhB = (const char*)(g_VrH + bh*Sq*DVq);
    const char* VlB = (const char*)(g_VrL + bh*Sq*DVq);

    for (int kt = kt0; kt <= qt; kt++) {
        const int t0 = kt * 64;
        // fill K (64x128) and V (64x256) hi/lo tiles
        {
            int row = tid >> 2, q4 = tid & 3;
            const char* kh = KhB + (size_t)(t0 + row)*256;
            const char* kl = KlB + (size_t)(t0 + row)*256;
            #pragma unroll
            for (int c = q4; c < 16; c += 4) {
                CP_ASYNC16(sb + ROFF_KH + row*RSTRQ + c*16, kh + c*16);
                CP_ASYNC16(sb + ROFF_KL + row*RSTRQ + c*16, kl + c*16);
            }
            const char* vh = VhB + (size_t)(t0 + row)*512;
            const char* vl = VlB + (size_t)(t0 + row)*512;
            #pragma unroll
            for (int c = q4; c < 32; c += 4) {
                CP_ASYNC16(sb + ROFF_VH + row*RSTRV + c*16, vh + c*16);
                CP_ASYNC16(sb + ROFF_VL + row*RSTRV + c*16, vl + c*16);
            }
        }
        CP_COMMIT();
        CP_WAIT(0);
        __syncthreads();

        // ---- phase 1: S[64x64] = Q K^T (3 split terms) ----
        float sc[2][2][4];
        #pragma unroll
        for (int a = 0; a < 2; a++)
            #pragma unroll
            for (int n = 0; n < 2; n++)
                #pragma unroll
                for (int e = 0; e < 4; e++) sc[a][n][e] = 0.f;

        #pragma unroll
        for (int ks = 0; ks < 8; ks++) {
            uint32_t ah[2][4], al[2][4];
            #pragma unroll
            for (int mi = 0; mi < 2; mi++) {
                uint32_t off = (uint32_t)(wm + mi*16 + (lane & 15))*RSTRQ
                             + (uint32_t)(ks*16 + ((lane >> 4) << 3))*2;
                LDSM4(ah[mi], sb + ROFF_QH + off);
                LDSM4(al[mi], sb + ROFF_QL + off);
            }
            uint32_t bh4[4], bl4[4];
            {
                uint32_t off = (uint32_t)(wn1 + ((lane >> 4) << 3) + (lane & 7))*RSTRQ
                             + (uint32_t)(ks*16 + (((lane >> 3) & 1) << 3))*2;
                LDSM4(bh4, sb + ROFF_KH + off);
                LDSM4(bl4, sb + ROFF_KL + off);
            }
            #pragma unroll
            for (int mi = 0; mi < 2; mi++) {
                #pragma unroll
                for (int ni = 0; ni < 2; ni++) {
                    uint32_t b0h = bh4[ni*2], b1h = bh4[ni*2+1];
                    uint32_t b0l = bl4[ni*2], b1l = bl4[ni*2+1];
                    MMA16816(sc[mi][ni], ah[mi], b0h, b1h);
                    MMA16816(sc[mi][ni], ah[mi], b0l, b1l);
                    MMA16816(sc[mi][ni], al[mi], b0h, b1h);
                }
            }
        }

        // rescale by gamma^(s0-t0), mask diagonal, split, store to Ss
        {
            float cfac = exp2f((float)(s0 - t0) * l2g);
            #pragma unroll
            for (int mi = 0; mi < 2; mi++) {
                #pragma unroll
                for (int half = 0; half < 2; half++) {
                    int n_l = wm + mi*16 + (lane >> 2) + half*8;
                    #pragma unroll
                    for (int ni = 0; ni < 2; ni++) {
                        int m_l = wn1 + ni*8 + (lane & 3)*2;
                        float v0 = sc[mi][ni][half*2]     * cfac;
                        float v1 = sc[mi][ni][half*2 + 1] * cfac;
                        if (kt == qt) {
                            if (n_l < m_l)     v0 = 0.f;
                            if (n_l < m_l + 1) v1 = 0.f;
                        }
                        __nv_bfloat16 h0, l0, h1, l1;
                        split2(v0, h0, l0); split2(v1, h1, l1);
                        uint32_t off = (uint32_t)n_l*RSTRS + (uint32_t)m_l*2;
                        *(__nv_bfloat162*)(smc + ROFF_SH + off) = __nv_bfloat162(h0, h1);
                        *(__nv_bfloat162*)(smc + ROFF_SL + off) = __nv_bfloat162(l0, l1);
                    }
                }
            }
        }
        __syncthreads();

        // ---- phase 2: Y += S V (3 split terms), V via ldmatrix.trans ----
        #pragma unroll
        for (int ks = 0; ks < 4; ks++) {
            uint32_t ah[2][4], al[2][4];
            #pragma unroll
            for (int mi = 0; mi < 2; mi++) {
                uint32_t off = (uint32_t)(wm + mi*16 + (lane & 15))*RSTRS
                             + (uint32_t)(ks*16 + ((lane >> 4) << 3))*2;
                LDSM4(ah[mi], sb + ROFF_SH + off);
                LDSM4(al[mi], sb + ROFF_SL + off);
            }
            uint32_t bvh[4][4], bvl[4][4];
            #pragma unroll
            for (int g = 0; g < 4; g++) {
                uint32_t off = (uint32_t)(ks*16 + (lane & 15))*RSTRV
                             + (uint32_t)(wn2 + g*16 + ((lane >> 4) << 3))*2;
                LDSM4T(bvh[g], sb + ROFF_VH + off);
                LDSM4T(bvl[g], sb + ROFF_VL + off);
            }
            #pragma unroll
            for (int mi = 0; mi < 2; mi++) {
                #pragma unroll
                for (int ni = 0; ni < 8; ni++) {
                    uint32_t b0h = bvh[ni >> 1][(ni & 1)*2], b1h = bvh[ni >> 1][(ni & 1)*2 + 1];
                    uint32_t b0l = bvl[ni >> 1][(ni & 1)*2], b1l = bvl[ni >> 1][(ni & 1)*2 + 1];
                    MMA16816(accY[mi][ni], ah[mi], b0h, b1h);
                    MMA16816(accY[mi][ni], ah[mi], b0l, b1l);
                    MMA16816(accY[mi][ni], al[mi], b0h, b1h);
                }
            }
        }
        __syncthreads();
    }

    // write Y: (b, s, h*DV + vd)
    #pragma unroll
    for (int mi = 0; mi < 2; mi++) {
        #pragma unroll
        for (int half = 0; half < 2; half++) {
            int r = s0 + wm + mi*16 + (lane >> 2) + half*8;
            float* yr = g_Y + (size_t)(b*Sq + r)*VDq + h*DVq;
            #pragma unroll
            for (int ni = 0; ni < 8; ni++) {
                int c = wn2 + ni*8 + (lane & 3)*2;
                *(float2*)(yr + c) = make_float2(accY[mi][ni][half*2], accY[mi][ni][half*2 + 1]);
            }
        }
    }
}

// ---------------- groupnorm + SiLU gate -> hi/lo bf16 ----------------
__global__ __launch_bounds__(256) void gn_gate_k(const float* __restrict__ gn_w,
                                                 const float* __restrict__ gn_b) {
    int row  = blockIdx.x;
    int head = threadIdx.x >> 5;
    int lane = threadIdx.x & 31;
    const float* Yr = g_Y + (size_t)row*VDq + head*DVq;
    float v[8]; float s = 0.f;
    #pragma unroll
    for (int i = 0; i < 8; i++) { v[i] = Yr[lane + i*32]; s += v[i]; }
    #pragma unroll
    for (int o = 16; o > 0; o >>= 1) s += __shfl_xor_sync(~0u, s, o);
    float mu = s * (1.0f/DVq);
    float vs = 0.f;
    #pragma unroll
    for (int i = 0; i < 8; i++) { float d = v[i]-mu; vs += d*d; }
    #pragma unroll
    for (int o = 16; o > 0; o >>= 1) vs += __shfl_xor_sync(~0u, vs, o);
    float rstd = rsqrtf(vs * (1.0f/DVq) + EPSq);
    const float* Gr = g_QKVG + (size_t)row*NCAT + 4096 + head*DVq;
    #pragma unroll
    for (int i = 0; i < 8; i++) {
        int c = head*DVq + lane + i*32;
        float y = (v[i]-mu)*rstd*gn_w[c] + gn_b[c];
        float g = Gr[lane + i*32];
        float sg = g / (1.0f + expf(-g));
        float o = sg * y;
        __nv_bfloat16 h, l; split2(o, h, l);
        g_YH[(size_t)row*VDq + c] = h;
        g_YL[(size_t)row*VDq + c] = l;
    }
}

// =====================================================================
// HMMA bf16-split GEMM (unchanged from R4)
// =====================================================================
#define LDT 40
#define MAT_ELE (128*LDT)
#define STG_BYTES (4*MAT_ELE*2)
#define GT_SMEM (2*STG_BYTES)

template<int EPI>
__global__ __launch_bounds__(256) void tgemm_k(
    const __nv_bfloat16* __restrict__ Ah, const __nv_bfloat16* __restrict__ Al,
    const __nv_bfloat16* __restrict__ Bh, const __nv_bfloat16* __restrict__ Bl,
    float* __restrict__ C,
    __nv_bfloat16* __restrict__ CH, __nv_bfloat16* __restrict__ CL,
    int M, int N, int K,
    const float* __restrict__ bias, const float* __restrict__ res)
{
    extern __shared__ __nv_bfloat16 smg[];
    const uint32_t sbase = s2u(smg);
    const int tid = threadIdx.x, lane = tid & 31, warp = tid >> 5;
    const int row0 = blockIdx.y * 128, col0 = blockIdx.x * 128;
    const int wm = (warp >> 2) * 64, wn = (warp & 3) * 32;

    const int r_ = tid >> 2, q_ = tid & 3;

    float acc[4][4][4];
    #pragma unroll
    for (int a = 0; a < 4; a++)
        #pragma unroll
        for (int b = 0; b < 4; b++)
            #pragma unroll
            for (int c = 0; c < 4; c++) acc[a][b][c] = 0.f;

    const int nch = K >> 5;

    auto load_stage = [&](int stage, int k0) {
        const uint32_t sb = sbase + (uint32_t)stage * STG_BYTES;
        #pragma unroll
        for (int mat = 0; mat < 4; mat++) {
            const __nv_bfloat16* base = (mat == 0) ? Ah : (mat == 1) ? Al : (mat == 2) ? Bh : Bl;
            const int grow0 = (mat < 2) ? row0 : col0;
            #pragma unroll
            for (int h = 0; h < 2; h++) {
                int row = r_ + h*64;
                const __nv_bfloat16* src = base + (size_t)(grow0 + row) * K + k0 + q_*8;
                uint32_t dst = sb + (uint32_t)(mat*MAT_ELE + row*LDT + q_*8) * 2;
                CP_ASYNC16(dst, src);
            }
        }
    };

    load_stage(0, 0);
    CP_COMMIT();

    for (int ch = 0; ch < nch; ch++) {
        if (ch + 1 < nch) {
            load_stage((ch + 1) & 1, (ch + 1) << 5);
            CP_COMMIT();
            CP_WAIT(1);
        } else {
            CP_WAIT(0);
        }
        __syncthreads();

        const uint32_t sb = sbase + (uint32_t)(ch & 1) * STG_BYTES;
        const uint32_t aHb = sb, aLb = sb + MAT_ELE*2;
        const uint32_t bHb = sb + 2*MAT_ELE*2, bLb = sb + 3*MAT_ELE*2;

        #pragma unroll
        for (int ks = 0; ks < 2; ks++) {
            uint32_t ah[4][4], al[4][4];
            #pragma unroll
            for (int mi = 0; mi < 4; mi++) {
                uint32_t off = (uint32_t)((wm + mi*16 + (lane & 15))*LDT + ks*16 + ((lane >> 4) << 3)) * 2;
                LDSM4(ah[mi], aHb + off);
                LDSM4(al[mi], aLb + off);
            }
            uint32_t bh[2][4], bl[2][4];
            #pragma unroll
            for (int gi = 0; gi < 2; gi++) {
                uint32_t off = (uint32_t)((wn + gi*16 + ((lane >> 4) << 3) + (lane & 7))*LDT
                                          + ks*16 + (((lane >> 3) & 1) << 3)) * 2;
                LDSM4(bh[gi], bHb + off);
                LDSM4(bl[gi], bLb + off);
            }
            #pragma unroll
            for (int mi = 0; mi < 4; mi++) {
                #pragma unroll
                for (int ni = 0; ni < 4; ni++) {
                    uint32_t b0h = bh[ni >> 1][(ni & 1)*2], b1h = bh[ni >> 1][(ni & 1)*2 + 1];
                    uint32_t b0l = bl[ni >> 1][(ni & 1)*2], b1l = bl[ni >> 1][(ni & 1)*2 + 1];
                    MMA16816(acc[mi][ni], ah[mi], b0h, b1h);
                    MMA16816(acc[mi][ni], ah[mi], b0l, b1l);
                    MMA16816(acc[mi][ni], al[mi], b0h, b1h);
                }
            }
        }
        __syncthreads();
    }

    const int rb = row0 + wm + (lane >> 2);
    const int cb = col0 + wn + (lane & 3)*2;
    #pragma unroll
    for (int mi = 0; mi < 4; mi++) {
        #pragma unroll
        for (int half = 0; half < 2; half++) {
            size_t r = (size_t)(rb + mi*16 + half*8);
            #pragma unroll
            for (int ni = 0; ni < 4; ni++) {
                int c = cb + ni*8;
                float v0 = acc[mi][ni][half*2 + 0];
                float v1 = acc[mi][ni][half*2 + 1];
                if (EPI == 1) {
                    v0 += bias[c];   v0 = 0.5f*v0*(1.0f + erff(v0*0.70710678118654752f));
                    v1 += bias[c+1]; v1 = 0.5f*v1*(1.0f + erff(v1*0.70710678118654752f));
                    __nv_bfloat16 h0, l0, h1, l1;
                    split2(v0, h0, l0); split2(v1, h1, l1);
                    *(__nv_bfloat162*)(CH + r*N + c) = __nv_bfloat162(h0, h1);
                    *(__nv_bfloat162*)(CL + r*N + c) = __nv_bfloat162(l0, l1);
                } else {
                    if (EPI == 2) { v0 += bias[c] + res[r*N + c]; v1 += bias[c+1] + res[r*N + c + 1]; }
                    else if (EPI == 3) { v0 += res[r*N + c]; v1 += res[r*N + c + 1]; }
                    *(float2*)(C + r*N + c) = make_float2(v0, v1);
                }
            }
        }
    }
}

// ---------------- launcher ----------------
extern "C" void kernel_launch(void* const* d_in, const int* in_sizes, int n_in,
                              void* d_out, int out_size) {
    const float* X      = (const float*)d_in[0];
    const float* Wq     = (const float*)d_in[1];
    const float* Wk     = (const float*)d_in[2];
    const float* Wv     = (const float*)d_in[3];
    const float* W_G    = (const float*)d_in[4];
    const float* W_O    = (const float*)d_in[5];
    const float* gn_w   = (const float*)d_in[6];
    const float* gn_b   = (const float*)d_in[7];
    const float* ln1_w  = (const float*)d_in[8];
    const float* ln1_b  = (const float*)d_in[9];
    const float* ln2_w  = (const float*)d_in[10];
    const float* ln2_b  = (const float*)d_in[11];
    const float* ffn_w1 = (const float*)d_in[12];
    const float* ffn_b1 = (const float*)d_in[13];
    const float* ffn_w2 = (const float*)d_in[14];
    const float* ffn_b2 = (const float*)d_in[15];
    float* out = (float*)d_out;

    float* p_Wcat;  cudaGetSymbolAddress((void**)&p_Wcat,  g_Wcat);
    float* p_QKVG;  cudaGetSymbolAddress((void**)&p_QKVG,  g_QKVG);
    float* p_X2;    cudaGetSymbolAddress((void**)&p_X2,    g_X2);
    __nv_bfloat16 *p_XnH, *p_XnL, *p_WcTH, *p_WcTL, *p_WOTH, *p_WOTL;
    __nv_bfloat16 *p_W1TH, *p_W1TL, *p_W2TH, *p_W2TL, *p_YH, *p_YL;
    __nv_bfloat16 *p_HnH, *p_HnL, *p_FfH, *p_FfL;
    cudaGetSymbolAddress((void**)&p_XnH,  g_XnH);  cudaGetSymbolAddress((void**)&p_XnL,  g_XnL);
    cudaGetSymbolAddress((void**)&p_WcTH, g_WcTH); cudaGetSymbolAddress((void**)&p_WcTL, g_WcTL);
    cudaGetSymbolAddress((void**)&p_WOTH, g_WOTH); cudaGetSymbolAddress((void**)&p_WOTL, g_WOTL);
    cudaGetSymbolAddress((void**)&p_W1TH, g_W1TH); cudaGetSymbolAddress((void**)&p_W1TL, g_W1TL);
    cudaGetSymbolAddress((void**)&p_W2TH, g_W2TH); cudaGetSymbolAddress((void**)&p_W2TL, g_W2TL);
    cudaGetSymbolAddress((void**)&p_YH,   g_YH);   cudaGetSymbolAddress((void**)&p_YL,   g_YL);
    cudaGetSymbolAddress((void**)&p_HnH,  g_HnH);  cudaGetSymbolAddress((void**)&p_HnL,  g_HnL);
    cudaGetSymbolAddress((void**)&p_FfH,  g_FfH);  cudaGetSymbolAddress((void**)&p_FfL,  g_FfL);

    cudaFuncSetAttribute(tgemm_k<0>, cudaFuncAttributeMaxDynamicSharedMemorySize, GT_SMEM);
    cudaFuncSetAttribute(tgemm_k<1>, cudaFuncAttributeMaxDynamicSharedMemorySize, GT_SMEM);
    cudaFuncSetAttribute(tgemm_k<2>, cudaFuncAttributeMaxDynamicSharedMemorySize, GT_SMEM);
    cudaFuncSetAttribute(tgemm_k<3>, cudaFuncAttributeMaxDynamicSharedMemorySize, GT_SMEM);
    cudaFuncSetAttribute(retention_t_k, cudaFuncAttributeMaxDynamicSharedMemorySize, RET_SMEM);

    // prep: repack + transposes(+split) + tables
    repack_k<<<(Dq*NCAT + 255)/256, 256>>>(Wq, Wk, Wv, W_G);
    xpos_tables_k<<<(Sq*64 + 255)/256, 256>>>();
    transpose_split_k<<<dim3(NCAT/32, Dq/32), 256>>>(p_Wcat, p_WcTH, p_WcTL, Dq, NCAT);
    transpose_split_k<<<dim3(Dq/32, VDq/32), 256>>>(W_O,    p_WOTH, p_WOTL, VDq, Dq);
    transpose_split_k<<<dim3(FFNq/32, Dq/32), 256>>>(ffn_w1, p_W1TH, p_W1TL, Dq, FFNq);
    transpose_split_k<<<dim3(Dq/32, FFNq/32), 256>>>(ffn_w2, p_W2TH, p_W2TL, FFNq, Dq);

    // LN1 -> hi/lo
    layernorm_split_k<<<Mq, 256>>>(X, ln1_w, ln1_b, p_XnH, p_XnL);

    // fused QKVG projection -> fp32
    tgemm_k<0><<<dim3(NCAT/128, Mq/128), 256, GT_SMEM>>>(
        p_XnH, p_XnL, p_WcTH, p_WcTL, p_QKVG, nullptr, nullptr, Mq, NCAT, Dq, nullptr, nullptr);

    // rotary + decay fold + split; V split
    xpos_apply_k<<<(Bq*Sq*Hq*64 + 255)/256, 256>>>();
    vsplit_k<<<(Bq*Sq*VDq/2 + 255)/256, 256>>>();

    // retention (tensor cores)
    retention_t_k<<<dim3(Sq/64, Hq, Bq), 256, RET_SMEM>>>();

    // groupnorm + gate -> hi/lo
    gn_gate_k<<<Mq, 256>>>(gn_w, gn_b);

    // output projection + residual -> X2 (fp32)
    tgemm_k<3><<<dim3(Dq/128, Mq/128), 256, GT_SMEM>>>(
        p_YH, p_YL, p_WOTH, p_WOTL, p_X2, nullptr, nullptr, Mq, Dq, VDq, nullptr, X);

    // LN2 -> hi/lo
    layernorm_split_k<<<Mq, 256>>>(p_X2, ln2_w, ln2_b, p_HnH, p_HnL);

    // FFN1 + gelu -> hi/lo
    tgemm_k<1><<<dim3(FFNq/128, Mq/128), 256, GT_SMEM>>>(
        p_HnH, p_HnL, p_W1TH, p_W1TL, nullptr, p_FfH, p_FfL, Mq, FFNq, Dq, ffn_b1, nullptr);

    // FFN2 + bias + residual -> out
    tgemm_k<2><<<dim3(Dq/128, Mq/128), 256, GT_SMEM>>>(
        p_FfH, p_FfL, p_W2TH, p_W2TL, out, nullptr, nullptr, Mq, Dq, FFNq, ffn_b2, p_X2);

    (void)in_sizes; (void)n_in; (void)out_size;
}

// round 13
// speedup vs baseline: 1.0007x; 1.0007x over previous
#include <cuda_runtime.h>
#include <cuda_bf16.h>
#include <math.h>
#include <stdint.h>

// Problem dims (fixed)
#define Bq   2
#define Sq   2048
#define Dq   1024
#define Hq   8
#define FFNq 4096
#define DKq  128
#define VDq  2048
#define DVq  256
#define Mq   (Bq*Sq)        // 4096 rows
#define NCAT 6144           // Q(1024) | K(1024) | V(2048) | G(2048)
#define EPSq 1e-5f

// ---------------- scratch (device globals; no allocations allowed) ----------------
__device__ float g_Wcat [(size_t)Dq*NCAT];            // packed [Wq|Wk|Wv|Wg] (D x NCAT)
__device__ float g_QKVG[(size_t)Mq*NCAT];
__device__ float g_Y  [(size_t)Mq*VDq];               // retention out (fp32)
__device__ float g_X2 [(size_t)Mq*Dq];
__device__ float g_cq[Sq*64], g_sq[Sq*64], g_ck[Sq*64], g_sk[Sq*64];

// hi/lo bf16 split operands for tensor-core GEMMs
__device__ __nv_bfloat16 g_XnH [(size_t)Mq*Dq],    g_XnL [(size_t)Mq*Dq];
__device__ __nv_bfloat16 g_WcTH[(size_t)NCAT*Dq],  g_WcTL[(size_t)NCAT*Dq];
__device__ __nv_bfloat16 g_WOTH[(size_t)Dq*VDq],   g_WOTL[(size_t)Dq*VDq];
__device__ __nv_bfloat16 g_W1TH[(size_t)FFNq*Dq],  g_W1TL[(size_t)FFNq*Dq];
__device__ __nv_bfloat16 g_W2TH[(size_t)Dq*FFNq],  g_W2TL[(size_t)Dq*FFNq];
__device__ __nv_bfloat16 g_YH  [(size_t)Mq*VDq],   g_YL  [(size_t)Mq*VDq];
__device__ __nv_bfloat16 g_HnH [(size_t)Mq*Dq],    g_HnL [(size_t)Mq*Dq];
__device__ __nv_bfloat16 g_FfH [(size_t)Mq*FFNq],  g_FfL [(size_t)Mq*FFNq];

// retention operands: decay-folded Q/K and V, hi/lo bf16, (b,h,s,*) layout
__device__ __nv_bfloat16 g_QrH[(size_t)Bq*Hq*Sq*DKq], g_QrL[(size_t)Bq*Hq*Sq*DKq];
__device__ __nv_bfloat16 g_KrH[(size_t)Bq*Hq*Sq*DKq], g_KrL[(size_t)Bq*Hq*Sq*DKq];
__device__ __nv_bfloat16 g_VrH[(size_t)Bq*Hq*Sq*DVq], g_VrL[(size_t)Bq*Hq*Sq*DVq];

// ---------------- helpers ----------------
__device__ __forceinline__ uint32_t s2u(const void* p) {
    uint32_t a;
    asm("{ .reg .u64 t; cvta.to.shared.u64 t, %1; cvt.u32.u64 %0, t; }" : "=r"(a) : "l"(p));
    return a;
}
__device__ __forceinline__ void split2(float v, __nv_bfloat16& h, __nv_bfloat16& l) {
    h = __float2bfloat16_rn(v);
    l = __float2bfloat16_rn(v - __bfloat162float(h));
}

#define LDSM4(r, addr) \
    asm volatile("ldmatrix.sync.aligned.m8n8.x4.shared.b16 {%0,%1,%2,%3}, [%4];" \
        : "=r"((r)[0]), "=r"((r)[1]), "=r"((r)[2]), "=r"((r)[3]) : "r"(addr))
#define LDSM4T(r, addr) \
    asm volatile("ldmatrix.sync.aligned.m8n8.x4.trans.shared.b16 {%0,%1,%2,%3}, [%4];" \
        : "=r"((r)[0]), "=r"((r)[1]), "=r"((r)[2]), "=r"((r)[3]) : "r"(addr))

#define MMA16816(d, a, b0v, b1v) \
    asm volatile("mma.sync.aligned.m16n8k16.row.col.f32.bf16.bf16.f32 " \
        "{%0,%1,%2,%3},{%4,%5,%6,%7},{%8,%9},{%0,%1,%2,%3};" \
        : "+f"((d)[0]), "+f"((d)[1]), "+f"((d)[2]), "+f"((d)[3]) \
        : "r"((a)[0]), "r"((a)[1]), "r"((a)[2]), "r"((a)[3]), "r"(b0v), "r"(b1v))

#define CP_ASYNC16(dst, src) \
    asm volatile("cp.async.cg.shared.global [%0], [%1], 16;" :: "r"(dst), "l"(src) : "memory")
#define CP_COMMIT() asm volatile("cp.async.commit_group;" ::: "memory")
#define CP_WAIT(n)  asm volatile("cp.async.wait_group %0;" :: "n"(n) : "memory")

// ---------------- weight repack: (H,D,DK)/(H,D,DV) -> plain (D, NCAT) ----------------
__global__ void repack_k(const float* __restrict__ Wq, const float* __restrict__ Wk,
                         const float* __restrict__ Wv, const float* __restrict__ Wg) {
    int idx = blockIdx.x * blockDim.x + threadIdx.x;
    if (idx >= Dq * NCAT) return;
    int d = idx / NCAT, n = idx % NCAT;
    float v;
    if (n < 1024)      { int h = n >> 7, k = n & 127;            v = Wq[((size_t)h*Dq + d)*DKq + k]; }
    else if (n < 2048) { int nn = n-1024; int h = nn>>7, k = nn&127; v = Wk[((size_t)h*Dq + d)*DKq + k]; }
    else if (n < 4096) { int nn = n-2048; int h = nn>>8, vv = nn&255; v = Wv[((size_t)h*Dq + d)*DVq + vv]; }
    else               { v = Wg[(size_t)d*VDq + (n-4096)]; }
    g_Wcat[idx] = v;
}

// ---------------- tiled transpose + hi/lo split ----------------
__global__ __launch_bounds__(256) void transpose_split_k(const float* __restrict__ src,
                                                         __nv_bfloat16* __restrict__ dH,
                                                         __nv_bfloat16* __restrict__ dL,
                                                         int R, int C) {
    __shared__ float t[32][33];
    int c0 = blockIdx.x * 32, r0 = blockIdx.y * 32;
    int x = threadIdx.x & 31, y = threadIdx.x >> 5;
    #pragma unroll
    for (int i = 0; i < 32; i += 8) t[y+i][x] = src[(size_t)(r0 + y + i)*C + c0 + x];
    __syncthreads();
    #pragma unroll
    for (int i = 0; i < 32; i += 8) {
        float v = t[x][y+i];
        size_t o = (size_t)(c0 + y + i)*R + r0 + x;
        __nv_bfloat16 h, l; split2(v, h, l);
        dH[o] = h; dL[o] = l;
    }
}

// ---------------- xpos tables ----------------
__global__ void xpos_tables_k() {
    int idx = blockIdx.x * blockDim.x + threadIdx.x;
    if (idx >= Sq*64) return;
    int pos = idx >> 6, i = idx & 63;
    float sv    = (2.0f*i + 0.4f*DKq) / (1.4f*DKq);
    float scale = powf(sv, (float)pos / 512.0f);
    float invf  = powf(10000.0f, -((float)i) / 64.0f);
    float ang   = (float)pos * invf;
    float s, c; sincosf(ang, &s, &c);
    g_cq[idx] = c*scale;  g_sq[idx] = s*scale;
    g_ck[idx] = c/scale;  g_sk[idx] = s/scale;
}

// ---------------- layernorm (rows of 1024) -> hi/lo bf16 ----------------
__global__ __launch_bounds__(256) void layernorm_split_k(const float* __restrict__ x,
                                                         const float* __restrict__ w,
                                                         const float* __restrict__ b,
                                                         __nv_bfloat16* __restrict__ yH,
                                                         __nv_bfloat16* __restrict__ yL) {
    int row = blockIdx.x;
    const float* xr = x + (size_t)row * Dq;
    float v[4]; float s = 0.f;
    #pragma unroll
    for (int i = 0; i < 4; i++) { v[i] = xr[threadIdx.x + i*256]; s += v[i]; }
    __shared__ float red[8];
    #pragma unroll
    for (int o = 16; o > 0; o >>= 1) s += __shfl_xor_sync(~0u, s, o);
    if ((threadIdx.x & 31) == 0) red[threadIdx.x >> 5] = s;
    __syncthreads();
    float mu = 0.f;
    #pragma unroll
    for (int i = 0; i < 8; i++) mu += red[i];
    mu *= (1.0f/Dq);
    __syncthreads();
    float vs = 0.f;
    #pragma unroll
    for (int i = 0; i < 4; i++) { float d = v[i]-mu; vs += d*d; }
    #pragma unroll
    for (int o = 16; o > 0; o >>= 1) vs += __shfl_xor_sync(~0u, vs, o);
    if ((threadIdx.x & 31) == 0) red[threadIdx.x >> 5] = vs;
    __syncthreads();
    float var = 0.f;
    #pragma unroll
    for (int i = 0; i < 8; i++) var += red[i];
    var *= (1.0f/Dq);
    float rstd = rsqrtf(var + EPSq);
    #pragma unroll
    for (int i = 0; i < 4; i++) {
        int c = threadIdx.x + i*256;
        float o = (v[i]-mu)*rstd*w[c] + b[c];
        __nv_bfloat16 h, l; split2(o, h, l);
        yH[(size_t)row*Dq + c] = h;
        yL[(size_t)row*Dq + c] = l;
    }
}

// ---------------- xpos apply + decay fold + hi/lo split ----------------
// Q row scaled by gamma^(s&63), K row scaled by gamma^(-(s&63))
__global__ void xpos_apply_k() {
    int idx = blockIdx.x * blockDim.x + threadIdx.x;
    if (idx >= Bq*Sq*Hq*64) return;
    int i = idx & 63, h = (idx >> 6) & 7, s = (idx >> 9) & (Sq-1), b = idx >> 20;
    int row = b*Sq + s;
    const float* qr = g_QKVG + (size_t)row * NCAT;
    int ti = s*64 + i;
    size_t ob = ((size_t)(b*Hq + h)*Sq + s)*DKq + 2*i;

    double lg = log(1.0/32.0) + (double)h * ((log(1.0/512.0) - log(1.0/32.0)) / 7.0);
    float gamma = 1.0f - (float)exp(lg);
    float l2g = log2f(gamma);
    int nl = s & 63;
    float qsc = exp2f((float)nl * l2g);     // <= 1
    float ksc = exp2f(-(float)nl * l2g);    // <= gamma^-63 ~ 7.4

    {
        float q0 = qr[h*128 + 2*i], q1 = qr[h*128 + 2*i + 1];
        float c = g_cq[ti], sn = g_sq[ti];
        float r0 = (q0*c - q1*sn) * qsc;
        float r1 = (q1*c + q0*sn) * qsc;
        __nv_bfloat16 h0, l0, h1, l1;
        split2(r0, h0, l0); split2(r1, h1, l1);
        g_QrH[ob] = h0; g_QrH[ob+1] = h1;
        g_QrL[ob] = l0; g_QrL[ob+1] = l1;
    }
    {
        float k0 = qr[1024 + h*128 + 2*i], k1 = qr[1024 + h*128 + 2*i + 1];
        float c = g_ck[ti], sn = g_sk[ti];
        float r0 = (k0*c - k1*sn) * ksc;
        float r1 = (k1*c + k0*sn) * ksc;
        __nv_bfloat16 h0, l0, h1, l1;
        split2(r0, h0, l0); split2(r1, h1, l1);
        g_KrH[ob] = h0; g_KrH[ob+1] = h1;
        g_KrL[ob] = l0; g_KrL[ob+1] = l1;
    }
}

// ---------------- V split: QKVG V-part -> (b,h,s,v) hi/lo bf16 ----------------
__global__ void vsplit_k() {
    int idx = blockIdx.x * blockDim.x + threadIdx.x;   // Bq*Sq*VDq / 2 (2 elems per thread)
    if (idx >= Bq*Sq*VDq/2) return;
    int e2 = idx * 2;
    int v = e2 & (VDq-1);
    int row = e2 >> 11;                   // b*Sq + s
    int h = v >> 8, vv = v & 255;
    const float* src = g_QKVG + (size_t)row*NCAT + 2048 + v;
    int b = row >> 11, s = row & (Sq-1);
    size_t ob = ((size_t)(b*Hq + h)*Sq + s)*DVq + vv;
    float a0 = src[0], a1 = src[1];
    __nv_bfloat16 h0, l0, h1, l1;
    split2(a0, h0, l0); split2(a1, h1, l1);
    *(__nv_bfloat162*)(g_VrH + ob) = __nv_bfloat162(h0, h1);
    *(__nv_bfloat162*)(g_VrL + ob) = __nv_bfloat162(l0, l1);
}

// =====================================================================
// retention on HMMA: per CTA (b, h, 64-query tile)
// phase 1: S = QK^T (3-term bf16 split), fp32 rescale by gamma^(s0-t0),
//          diag mask, split to hi/lo in SMEM
// phase 2: Y += S V (3-term), Y fp32 in registers
// decay folded into Q/K at xpos time; tile skip when factor < 2^-40.
// =====================================================================
#define RSTRQ 272   // (128+8) bf16 * 2B
#define RSTRV 528   // (256+8) bf16 * 2B
#define RSTRS 144   // (64+8)  bf16 * 2B
#define ROFF_QH 0
#define ROFF_QL 17408
#define ROFF_KH 34816
#define ROFF_KL 52224
#define ROFF_VH 69632
#define ROFF_VL 103424
#define ROFF_SH 137216
#define ROFF_SL 146432
#define RET_SMEM 155648

__global__ __launch_bounds__(256) void retention_t_k() {
    extern __shared__ char smc[];
    const uint32_t sb = s2u(smc);
    const int tid = threadIdx.x, lane = tid & 31, warp = tid >> 5;
    const int qt = 31 - blockIdx.x, h = blockIdx.y, b = blockIdx.z;
    const int s0 = qt * 64;

    double lg = log(1.0/32.0) + (double)h * ((log(1.0/512.0) - log(1.0/32.0)) / 7.0);
    float gamma = 1.0f - (float)exp(lg);
    float l2g = log2f(gamma);
    float nl2g = -l2g;

    const size_t bh = (size_t)(b*Hq + h);
    const char* Qh = (const char*)(g_QrH + (bh*Sq + s0)*DKq);
    const char* Ql = (const char*)(g_QrL + (bh*Sq + s0)*DKq);

    // load Q tile once (64 x 128 bf16 hi/lo)
    {
        int row = tid >> 2, q4 = tid & 3;
        #pragma unroll
        for (int c = q4; c < 16; c += 4) {
            CP_ASYNC16(sb + ROFF_QH + row*RSTRQ + c*16, Qh + row*256 + c*16);
            CP_ASYNC16(sb + ROFF_QL + row*RSTRQ + c*16, Ql + row*256 + c*16);
        }
        CP_COMMIT();
    }

    // decay-truncation start tile
    int kt0 = 0;
    {
        float ktf = ((float)s0 - 63.0f - 40.0f/nl2g) * (1.0f/64.0f);
        if (ktf > 0.0f) kt0 = (int)ceilf(ktf);
        if (kt0 > qt) kt0 = qt;
        if (kt0 < 0) kt0 = 0;
    }

    const int wm = (warp >> 2) * 32;      // query rows (both phases)
    const int wn1 = (warp & 3) * 16;      // phase1 key cols
    const int wn2 = (warp & 3) * 64;      // phase2 vd cols

    float accY[2][8][4];
    #pragma unroll
    for (int a = 0; a < 2; a++)
        #pragma unroll
        for (int n = 0; n < 8; n++)
            #pragma unroll
            for (int e = 0; e < 4; e++) accY[a][n][e] = 0.f;

    const char* KhB = (const char*)(g_KrH + bh*Sq*DKq);
    const char* KlB = (const char*)(g_KrL + bh*Sq*DKq);
    const char* VhB = (const char*)(g_VrH + bh*Sq*DVq);
    const char* VlB = (const char*)(g_VrL + bh*Sq*DVq);

    for (int kt = kt0; kt <= qt; kt++) {
        const int t0 = kt * 64;
        // fill K (64x128) and V (64x256) hi/lo tiles
        {
            int row = tid >> 2, q4 = tid & 3;
            const char* kh = KhB + (size_t)(t0 + row)*256;
            const char* kl = KlB + (size_t)(t0 + row)*256;
            #pragma unroll
            for (int c = q4; c < 16; c += 4) {
                CP_ASYNC16(sb + ROFF_KH + row*RSTRQ + c*16, kh + c*16);
                CP_ASYNC16(sb + ROFF_KL + row*RSTRQ + c*16, kl + c*16);
            }
            const char* vh = VhB + (size_t)(t0 + row)*512;
            const char* vl = VlB + (size_t)(t0 + row)*512;
            #pragma unroll
            for (int c = q4; c < 32; c += 4) {
                CP_ASYNC16(sb + ROFF_VH + row*RSTRV + c*16, vh + c*16);
                CP_ASYNC16(sb + ROFF_VL + row*RSTRV + c*16, vl + c*16);
            }
        }
        CP_COMMIT();
        CP_WAIT(0);
        __syncthreads();

        // ---- phase 1: S[64x64] = Q K^T (3 split terms) ----
        float sc[2][2][4];
        #pragma unroll
        for (int a = 0; a < 2; a++)
            #pragma unroll
            for (int n = 0; n < 2; n++)
                #pragma unroll
                for (int e = 0; e < 4; e++) sc[a][n][e] = 0.f;

        #pragma unroll
        for (int ks = 0; ks < 8; ks++) {
            uint32_t ah[2][4], al[2][4];
            #pragma unroll
            for (int mi = 0; mi < 2; mi++) {
                uint32_t off = (uint32_t)(wm + mi*16 + (lane & 15))*RSTRQ
                             + (uint32_t)(ks*16 + ((lane >> 4) << 3))*2;
                LDSM4(ah[mi], sb + ROFF_QH + off);
                LDSM4(al[mi], sb + ROFF_QL + off);
            }
            uint32_t bh4[4], bl4[4];
            {
                uint32_t off = (uint32_t)(wn1 + ((lane >> 4) << 3) + (lane & 7))*RSTRQ
                             + (uint32_t)(ks*16 + (((lane >> 3) & 1) << 3))*2;
                LDSM4(bh4, sb + ROFF_KH + off);
                LDSM4(bl4, sb + ROFF_KL + off);
            }
            #pragma unroll
            for (int mi = 0; mi < 2; mi++) {
                #pragma unroll
                for (int ni = 0; ni < 2; ni++) {
                    uint32_t b0h = bh4[ni*2], b1h = bh4[ni*2+1];
                    uint32_t b0l = bl4[ni*2], b1l = bl4[ni*2+1];
                    MMA16816(sc[mi][ni], ah[mi], b0h, b1h);
                    MMA16816(sc[mi][ni], ah[mi], b0l, b1l);
                    MMA16816(sc[mi][ni], al[mi], b0h, b1h);
                }
            }
        }

        // rescale by gamma^(s0-t0), mask diagonal, split, store to Ss
        {
            float cfac = exp2f((float)(s0 - t0) * l2g);
            #pragma unroll
            for (int mi = 0; mi < 2; mi++) {
                #pragma unroll
                for (int half = 0; half < 2; half++) {
                    int n_l = wm + mi*16 + (lane >> 2) + half*8;
                    #pragma unroll
                    for (int ni = 0; ni < 2; ni++) {
                        int m_l = wn1 + ni*8 + (lane & 3)*2;
                        float v0 = sc[mi][ni][half*2]     * cfac;
                        float v1 = sc[mi][ni][half*2 + 1] * cfac;
                        if (kt == qt) {
                            if (n_l < m_l)     v0 = 0.f;
                            if (n_l < m_l + 1) v1 = 0.f;
                        }
                        __nv_bfloat16 h0, l0, h1, l1;
                        split2(v0, h0, l0); split2(v1, h1, l1);
                        uint32_t off = (uint32_t)n_l*RSTRS + (uint32_t)m_l*2;
                        *(__nv_bfloat162*)(smc + ROFF_SH + off) = __nv_bfloat162(h0, h1);
                        *(__nv_bfloat162*)(smc + ROFF_SL + off) = __nv_bfloat162(l0, l1);
                    }
                }
            }
        }
        __syncthreads();

        // ---- phase 2: Y += S V (3 split terms), V via ldmatrix.trans ----
        #pragma unroll
        for (int ks = 0; ks < 4; ks++) {
            uint32_t ah[2][4], al[2][4];
            #pragma unroll
            for (int mi = 0; mi < 2; mi++) {
                uint32_t off = (uint32_t)(wm + mi*16 + (lane & 15))*RSTRS
                             + (uint32_t)(ks*16 + ((lane >> 4) << 3))*2;
                LDSM4(ah[mi], sb + ROFF_SH + off);
                LDSM4(al[mi], sb + ROFF_SL + off);
            }
            uint32_t bvh[4][4], bvl[4][4];
            #pragma unroll
            for (int g = 0; g < 4; g++) {
                uint32_t off = (uint32_t)(ks*16 + (lane & 15))*RSTRV
                             + (uint32_t)(wn2 + g*16 + ((lane >> 4) << 3))*2;
                LDSM4T(bvh[g], sb + ROFF_VH + off);
                LDSM4T(bvl[g], sb + ROFF_VL + off);
            }
            #pragma unroll
            for (int mi = 0; mi < 2; mi++) {
                #pragma unroll
                for (int ni = 0; ni < 8; ni++) {
                    uint32_t b0h = bvh[ni >> 1][(ni & 1)*2], b1h = bvh[ni >> 1][(ni & 1)*2 + 1];
                    uint32_t b0l = bvl[ni >> 1][(ni & 1)*2], b1l = bvl[ni >> 1][(ni & 1)*2 + 1];
                    MMA16816(accY[mi][ni], ah[mi], b0h, b1h);
                    MMA16816(accY[mi][ni], ah[mi], b0l, b1l);
                    MMA16816(accY[mi][ni], al[mi], b0h, b1h);
                }
            }
        }
        __syncthreads();
    }

    // write Y: (b, s, h*DV + vd)
    #pragma unroll
    for (int mi = 0; mi < 2; mi++) {
        #pragma unroll
        for (int half = 0; half < 2; half++) {
            int r = s0 + wm + mi*16 + (lane >> 2) + half*8;
            float* yr = g_Y + (size_t)(b*Sq + r)*VDq + h*DVq;
            #pragma unroll
            for (int ni = 0; ni < 8; ni++) {
                int c = wn2 + ni*8 + (lane & 3)*2;
                *(float2*)(yr + c) = make_float2(accY[mi][ni][half*2], accY[mi][ni][half*2 + 1]);
            }
        }
    }
}

// ---------------- groupnorm + SiLU gate -> hi/lo bf16 ----------------
__global__ __launch_bounds__(256) void gn_gate_k(const float* __restrict__ gn_w,
                                                 const float* __restrict__ gn_b) {
    int row  = blockIdx.x;
    int head = threadIdx.x >> 5;
    int lane = threadIdx.x & 31;
    const float* Yr = g_Y + (size_t)row*VDq + head*DVq;
    float v[8]; float s = 0.f;
    #pragma unroll
    for (int i = 0; i < 8; i++) { v[i] = Yr[lane + i*32]; s += v[i]; }
    #pragma unroll
    for (int o = 16; o > 0; o >>= 1) s += __shfl_xor_sync(~0u, s, o);
    float mu = s * (1.0f/DVq);
    float vs = 0.f;
    #pragma unroll
    for (int i = 0; i < 8; i++) { float d = v[i]-mu; vs += d*d; }
    #pragma unroll
    for (int o = 16; o > 0; o >>= 1) vs += __shfl_xor_sync(~0u, vs, o);
    float rstd = rsqrtf(vs * (1.0f/DVq) + EPSq);
    const float* Gr = g_QKVG + (size_t)row*NCAT + 4096 + head*DVq;
    #pragma unroll
    for (int i = 0; i < 8; i++) {
        int c = head*DVq + lane + i*32;
        float y = (v[i]-mu)*rstd*gn_w[c] + gn_b[c];
        float g = Gr[lane + i*32];
        float sg = g / (1.0f + expf(-g));
        float o = sg * y;
        __nv_bfloat16 h, l; split2(o, h, l);
        g_YH[(size_t)row*VDq + c] = h;
        g_YL[(size_t)row*VDq + c] = l;
    }
}

// =====================================================================
// HMMA bf16-split GEMM (unchanged from R4)
// =====================================================================
#define LDT 40
#define MAT_ELE (128*LDT)
#define STG_BYTES (4*MAT_ELE*2)
#define GT_SMEM (2*STG_BYTES)

template<int EPI>
__global__ __launch_bounds__(256) void tgemm_k(
    const __nv_bfloat16* __restrict__ Ah, const __nv_bfloat16* __restrict__ Al,
    const __nv_bfloat16* __restrict__ Bh, const __nv_bfloat16* __restrict__ Bl,
    float* __restrict__ C,
    __nv_bfloat16* __restrict__ CH, __nv_bfloat16* __restrict__ CL,
    int M, int N, int K,
    const float* __restrict__ bias, const float* __restrict__ res)
{
    extern __shared__ __nv_bfloat16 smg[];
    const uint32_t sbase = s2u(smg);
    const int tid = threadIdx.x, lane = tid & 31, warp = tid >> 5;
    const int row0 = blockIdx.y * 128, col0 = blockIdx.x * 128;
    const int wm = (warp >> 2) * 64, wn = (warp & 3) * 32;

    const int r_ = tid >> 2, q_ = tid & 3;

    float acc[4][4][4];
    #pragma unroll
    for (int a = 0; a < 4; a++)
        #pragma unroll
        for (int b = 0; b < 4; b++)
            #pragma unroll
            for (int c = 0; c < 4; c++) acc[a][b][c] = 0.f;

    const int nch = K >> 5;

    auto load_stage = [&](int stage, int k0) {
        const uint32_t sb = sbase + (uint32_t)stage * STG_BYTES;
        #pragma unroll
        for (int mat = 0; mat < 4; mat++) {
            const __nv_bfloat16* base = (mat == 0) ? Ah : (mat == 1) ? Al : (mat == 2) ? Bh : Bl;
            const int grow0 = (mat < 2) ? row0 : col0;
            #pragma unroll
            for (int h = 0; h < 2; h++) {
                int row = r_ + h*64;
                const __nv_bfloat16* src = base + (size_t)(grow0 + row) * K + k0 + q_*8;
                uint32_t dst = sb + (uint32_t)(mat*MAT_ELE + row*LDT + q_*8) * 2;
                CP_ASYNC16(dst, src);
            }
        }
    };

    load_stage(0, 0);
    CP_COMMIT();

    for (int ch = 0; ch < nch; ch++) {
        if (ch + 1 < nch) {
            load_stage((ch + 1) & 1, (ch + 1) << 5);
            CP_COMMIT();
            CP_WAIT(1);
        } else {
            CP_WAIT(0);
        }
        __syncthreads();

        const uint32_t sb = sbase + (uint32_t)(ch & 1) * STG_BYTES;
        const uint32_t aHb = sb, aLb = sb + MAT_ELE*2;
        const uint32_t bHb = sb + 2*MAT_ELE*2, bLb = sb + 3*MAT_ELE*2;

        #pragma unroll
        for (int ks = 0; ks < 2; ks++) {
            uint32_t ah[4][4], al[4][4];
            #pragma unroll
            for (int mi = 0; mi < 4; mi++) {
                uint32_t off = (uint32_t)((wm + mi*16 + (lane & 15))*LDT + ks*16 + ((lane >> 4) << 3)) * 2;
                LDSM4(ah[mi], aHb + off);
                LDSM4(al[mi], aLb + off);
            }
            uint32_t bh[2][4], bl[2][4];
            #pragma unroll
            for (int gi = 0; gi < 2; gi++) {
                uint32_t off = (uint32_t)((wn + gi*16 + ((lane >> 4) << 3) + (lane & 7))*LDT
                                          + ks*16 + (((lane >> 3) & 1) << 3)) * 2;
                LDSM4(bh[gi], bHb + off);
                LDSM4(bl[gi], bLb + off);
            }
            #pragma unroll
            for (int mi = 0; mi < 4; mi++) {
                #pragma unroll
                for (int ni = 0; ni < 4; ni++) {
                    uint32_t b0h = bh[ni >> 1][(ni & 1)*2], b1h = bh[ni >> 1][(ni & 1)*2 + 1];
                    uint32_t b0l = bl[ni >> 1][(ni & 1)*2], b1l = bl[ni >> 1][(ni & 1)*2 + 1];
                    MMA16816(acc[mi][ni], ah[mi], b0h, b1h);
                    MMA16816(acc[mi][ni], ah[mi], b0l, b1l);
                    MMA16816(acc[mi][ni], al[mi], b0h, b1h);
                }
            }
        }
        __syncthreads();
    }

    const int rb = row0 + wm + (lane >> 2);
    const int cb = col0 + wn + (lane & 3)*2;
    #pragma unroll
    for (int mi = 0; mi < 4; mi++) {
        #pragma unroll
        for (int half = 0; half < 2; half++) {
            size_t r = (size_t)(rb + mi*16 + half*8);
            #pragma unroll
            for (int ni = 0; ni < 4; ni++) {
                int c = cb + ni*8;
                float v0 = acc[mi][ni][half*2 + 0];
                float v1 = acc[mi][ni][half*2 + 1];
                if (EPI == 1) {
                    v0 += bias[c];   v0 = 0.5f*v0*(1.0f + erff(v0*0.70710678118654752f));
                    v1 += bias[c+1]; v1 = 0.5f*v1*(1.0f + erff(v1*0.70710678118654752f));
                    __nv_bfloat16 h0, l0, h1, l1;
                    split2(v0, h0, l0); split2(v1, h1, l1);
                    *(__nv_bfloat162*)(CH + r*N + c) = __nv_bfloat162(h0, h1);
                    *(__nv_bfloat162*)(CL + r*N + c) = __nv_bfloat162(l0, l1);
                } else {
                    if (EPI == 2) { v0 += bias[c] + res[r*N + c]; v1 += bias[c+1] + res[r*N + c + 1]; }
                    else if (EPI == 3) { v0 += res[r*N + c]; v1 += res[r*N + c + 1]; }
                    *(float2*)(C + r*N + c) = make_float2(v0, v1);
                }
            }
        }
    }
}

// ---------------- launcher ----------------
extern "C" void kernel_launch(void* const* d_in, const int* in_sizes, int n_in,
                              void* d_out, int out_size) {
    const float* X      = (const float*)d_in[0];
    const float* Wq     = (const float*)d_in[1];
    const float* Wk     = (const float*)d_in[2];
    const float* Wv     = (const float*)d_in[3];
    const float* W_G    = (const float*)d_in[4];
    const float* W_O    = (const float*)d_in[5];
    const float* gn_w   = (const float*)d_in[6];
    const float* gn_b   = (const float*)d_in[7];
    const float* ln1_w  = (const float*)d_in[8];
    const float* ln1_b  = (const float*)d_in[9];
    const float* ln2_w  = (const float*)d_in[10];
    const float* ln2_b  = (const float*)d_in[11];
    const float* ffn_w1 = (const float*)d_in[12];
    const float* ffn_b1 = (const float*)d_in[13];
    const float* ffn_w2 = (const float*)d_in[14];
    const float* ffn_b2 = (const float*)d_in[15];
    float* out = (float*)d_out;

    float* p_Wcat;  cudaGetSymbolAddress((void**)&p_Wcat,  g_Wcat);
    float* p_QKVG;  cudaGetSymbolAddress((void**)&p_QKVG,  g_QKVG);
    float* p_X2;    cudaGetSymbolAddress((void**)&p_X2,    g_X2);
    __nv_bfloat16 *p_XnH, *p_XnL, *p_WcTH, *p_WcTL, *p_WOTH, *p_WOTL;
    __nv_bfloat16 *p_W1TH, *p_W1TL, *p_W2TH, *p_W2TL, *p_YH, *p_YL;
    __nv_bfloat16 *p_HnH, *p_HnL, *p_FfH, *p_FfL;
    cudaGetSymbolAddress((void**)&p_XnH,  g_XnH);  cudaGetSymbolAddress((void**)&p_XnL,  g_XnL);
    cudaGetSymbolAddress((void**)&p_WcTH, g_WcTH); cudaGetSymbolAddress((void**)&p_WcTL, g_WcTL);
    cudaGetSymbolAddress((void**)&p_WOTH, g_WOTH); cudaGetSymbolAddress((void**)&p_WOTL, g_WOTL);
    cudaGetSymbolAddress((void**)&p_W1TH, g_W1TH); cudaGetSymbolAddress((void**)&p_W1TL, g_W1TL);
    cudaGetSymbolAddress((void**)&p_W2TH, g_W2TH); cudaGetSymbolAddress((void**)&p_W2TL, g_W2TL);
    cudaGetSymbolAddress((void**)&p_YH,   g_YH);   cudaGetSymbolAddress((void**)&p_YL,   g_YL);
    cudaGetSymbolAddress((void**)&p_HnH,  g_HnH);  cudaGetSymbolAddress((void**)&p_HnL,  g_HnL);
    cudaGetSymbolAddress((void**)&p_FfH,  g_FfH);  cudaGetSymbolAddress((void**)&p_FfL,  g_FfL);

    cudaFuncSetAttribute(tgemm_k<0>, cudaFuncAttributeMaxDynamicSharedMemorySize, GT_SMEM);
    cudaFuncSetAttribute(tgemm_k<1>, cudaFuncAttributeMaxDynamicSharedMemorySize, GT_SMEM);
    cudaFuncSetAttribute(tgemm_k<2>, cudaFuncAttributeMaxDynamicSharedMemorySize, GT_SMEM);
    cudaFuncSetAttribute(tgemm_k<3>, cudaFuncAttributeMaxDynamicSharedMemorySize, GT_SMEM);
    cudaFuncSetAttribute(retention_t_k, cudaFuncAttributeMaxDynamicSharedMemorySize, RET_SMEM);

    // prep: repack + transposes(+split) + tables
    repack_k<<<(Dq*NCAT + 255)/256, 256>>>(Wq, Wk, Wv, W_G);
    xpos_tables_k<<<(Sq*64 + 255)/256, 256>>>();
    transpose_split_k<<<dim3(NCAT/32, Dq/32), 256>>>(p_Wcat, p_WcTH, p_WcTL, Dq, NCAT);
    transpose_split_k<<<dim3(Dq/32, VDq/32), 256>>>(W_O,    p_WOTH, p_WOTL, VDq, Dq);
    transpose_split_k<<<dim3(FFNq/32, Dq/32), 256>>>(ffn_w1, p_W1TH, p_W1TL, Dq, FFNq);
    transpose_split_k<<<dim3(Dq/32, FFNq/32), 256>>>(ffn_w2, p_W2TH, p_W2TL, FFNq, Dq);

    // LN1 -> hi/lo
    layernorm_split_k<<<Mq, 256>>>(X, ln1_w, ln1_b, p_XnH, p_XnL);

    // fused QKVG projection -> fp32
    tgemm_k<0><<<dim3(NCAT/128, Mq/128), 256, GT_SMEM>>>(
        p_XnH, p_XnL, p_WcTH, p_WcTL, p_QKVG, nullptr, nullptr, Mq, NCAT, Dq, nullptr, nullptr);

    // rotary + decay fold + split; V split
    xpos_apply_k<<<(Bq*Sq*Hq*64 + 255)/256, 256>>>();
    vsplit_k<<<(Bq*Sq*VDq/2 + 255)/256, 256>>>();

    // retention (tensor cores)
    retention_t_k<<<dim3(Sq/64, Hq, Bq), 256, RET_SMEM>>>();

    // groupnorm + gate -> hi/lo
    gn_gate_k<<<Mq, 256>>>(gn_w, gn_b);

    // output projection + residual -> X2 (fp32)
    tgemm_k<3><<<dim3(Dq/128, Mq/128), 256, GT_SMEM>>>(
        p_YH, p_YL, p_WOTH, p_WOTL, p_X2, nullptr, nullptr, Mq, Dq, VDq, nullptr, X);

    // LN2 -> hi/lo
    layernorm_split_k<<<Mq, 256>>>(p_X2, ln2_w, ln2_b, p_HnH, p_HnL);

    // FFN1 + gelu -> hi/lo
    tgemm_k<1><<<dim3(FFNq/128, Mq/128), 256, GT_SMEM>>>(
        p_HnH, p_HnL, p_W1TH, p_W1TL, nullptr, p_FfH, p_FfL, Mq, FFNq, Dq, ffn_b1, nullptr);

    // FFN2 + bias + residual -> out
    tgemm_k<2><<<dim3(Dq/128, Mq/128), 256, GT_SMEM>>>(
        p_FfH, p_FfL, p_W2TH, p_W2TL, out, nullptr, nullptr, Mq, Dq, FFNq, ffn_b2, p_X2);

    (void)in_sizes; (void)n_in; (void)out_size;
}

// round 15
// speedup vs baseline: 1.1198x; 1.1190x over previous
#include <cuda_runtime.h>
#include <cuda_bf16.h>
#include <math.h>
#include <stdint.h>

// Problem dims (fixed)
#define Bq   2
#define Sq   2048
#define Dq   1024
#define Hq   8
#define FFNq 4096
#define DKq  128
#define VDq  2048
#define DVq  256
#define Mq   (Bq*Sq)        // 4096 rows
#define NCAT 6144           // Q(1024) | K(1024) | V(2048) | G(2048)
#define EPSq 1e-5f
#define NCH  32             // chunks of 64 along S

// ---------------- scratch (device globals; no allocations allowed) ----------------
__device__ float g_Wcat [(size_t)Dq*NCAT];            // packed [Wq|Wk|Wv|Wg] (D x NCAT)
__device__ float g_QKVG[(size_t)Mq*NCAT];
__device__ float g_Y  [(size_t)Mq*VDq];               // retention out (fp32)
__device__ float g_X2 [(size_t)Mq*Dq];
__device__ float g_cq[Sq*64], g_sq[Sq*64], g_ck[Sq*64], g_sk[Sq*64];

// hi/lo bf16 split operands for tensor-core GEMMs
__device__ __nv_bfloat16 g_XnH [(size_t)Mq*Dq],    g_XnL [(size_t)Mq*Dq];
__device__ __nv_bfloat16 g_WcTH[(size_t)NCAT*Dq],  g_WcTL[(size_t)NCAT*Dq];
__device__ __nv_bfloat16 g_WOTH[(size_t)Dq*VDq],   g_WOTL[(size_t)Dq*VDq];
__device__ __nv_bfloat16 g_W1TH[(size_t)FFNq*Dq],  g_W1TL[(size_t)FFNq*Dq];
__device__ __nv_bfloat16 g_W2TH[(size_t)Dq*FFNq],  g_W2TL[(size_t)Dq*FFNq];
__device__ __nv_bfloat16 g_YH  [(size_t)Mq*VDq],   g_YL  [(size_t)Mq*VDq];
__device__ __nv_bfloat16 g_HnH [(size_t)Mq*Dq],    g_HnL [(size_t)Mq*Dq];
__device__ __nv_bfloat16 g_FfH [(size_t)Mq*FFNq],  g_FfL [(size_t)Mq*FFNq];

// retention operands: decay-folded Q/K and V, hi/lo bf16, (b,h,s,*) layout
__device__ __nv_bfloat16 g_QrH[(size_t)Bq*Hq*Sq*DKq], g_QrL[(size_t)Bq*Hq*Sq*DKq];
__device__ __nv_bfloat16 g_KrH[(size_t)Bq*Hq*Sq*DKq], g_KrL[(size_t)Bq*Hq*Sq*DKq];
__device__ __nv_bfloat16 g_VrH[(size_t)Bq*Hq*Sq*DVq], g_VrL[(size_t)Bq*Hq*Sq*DVq];

// chunked-recurrent retention state
__device__ float         g_A [(size_t)Bq*Hq*NCH*DKq*DVq];   // per-chunk K^T V (fp32)
__device__ __nv_bfloat16 g_PH[(size_t)Bq*Hq*NCH*DKq*DVq];   // prefix state hi
__device__ __nv_bfloat16 g_PL[(size_t)Bq*Hq*NCH*DKq*DVq];   // prefix state lo

// ---------------- helpers ----------------
__device__ __forceinline__ uint32_t s2u(const void* p) {
    uint32_t a;
    asm("{ .reg .u64 t; cvta.to.shared.u64 t, %1; cvt.u32.u64 %0, t; }" : "=r"(a) : "l"(p));
    return a;
}
__device__ __forceinline__ void split2(float v, __nv_bfloat16& h, __nv_bfloat16& l) {
    h = __float2bfloat16_rn(v);
    l = __float2bfloat16_rn(v - __bfloat162float(h));
}

#define LDSM4(r, addr) \
    asm volatile("ldmatrix.sync.aligned.m8n8.x4.shared.b16 {%0,%1,%2,%3}, [%4];" \
        : "=r"((r)[0]), "=r"((r)[1]), "=r"((r)[2]), "=r"((r)[3]) : "r"(addr))
#define LDSM4T(r, addr) \
    asm volatile("ldmatrix.sync.aligned.m8n8.x4.trans.shared.b16 {%0,%1,%2,%3}, [%4];" \
        : "=r"((r)[0]), "=r"((r)[1]), "=r"((r)[2]), "=r"((r)[3]) : "r"(addr))

#define MMA16816(d, a, b0v, b1v) \
    asm volatile("mma.sync.aligned.m16n8k16.row.col.f32.bf16.bf16.f32 " \
        "{%0,%1,%2,%3},{%4,%5,%6,%7},{%8,%9},{%0,%1,%2,%3};" \
        : "+f"((d)[0]), "+f"((d)[1]), "+f"((d)[2]), "+f"((d)[3]) \
        : "r"((a)[0]), "r"((a)[1]), "r"((a)[2]), "r"((a)[3]), "r"(b0v), "r"(b1v))

#define CP_ASYNC16(dst, src) \
    asm volatile("cp.async.cg.shared.global [%0], [%1], 16;" :: "r"(dst), "l"(src) : "memory")
#define CP_COMMIT() asm volatile("cp.async.commit_group;" ::: "memory")
#define CP_WAIT(n)  asm volatile("cp.async.wait_group %0;" :: "n"(n) : "memory")

// ---------------- weight repack: (H,D,DK)/(H,D,DV) -> plain (D, NCAT) ----------------
__global__ void repack_k(const float* __restrict__ Wq, const float* __restrict__ Wk,
                         const float* __restrict__ Wv, const float* __restrict__ Wg) {
    int idx = blockIdx.x * blockDim.x + threadIdx.x;
    if (idx >= Dq * NCAT) return;
    int d = idx / NCAT, n = idx % NCAT;
    float v;
    if (n < 1024)      { int h = n >> 7, k = n & 127;            v = Wq[((size_t)h*Dq + d)*DKq + k]; }
    else if (n < 2048) { int nn = n-1024; int h = nn>>7, k = nn&127; v = Wk[((size_t)h*Dq + d)*DKq + k]; }
    else if (n < 4096) { int nn = n-2048; int h = nn>>8, vv = nn&255; v = Wv[((size_t)h*Dq + d)*DVq + vv]; }
    else               { v = Wg[(size_t)d*VDq + (n-4096)]; }
    g_Wcat[idx] = v;
}

// ---------------- tiled transpose + hi/lo split ----------------
__global__ __launch_bounds__(256) void transpose_split_k(const float* __restrict__ src,
                                                         __nv_bfloat16* __restrict__ dH,
                                                         __nv_bfloat16* __restrict__ dL,
                                                         int R, int C) {
    __shared__ float t[32][33];
    int c0 = blockIdx.x * 32, r0 = blockIdx.y * 32;
    int x = threadIdx.x & 31, y = threadIdx.x >> 5;
    #pragma unroll
    for (int i = 0; i < 32; i += 8) t[y+i][x] = src[(size_t)(r0 + y + i)*C + c0 + x];
    __syncthreads();
    #pragma unroll
    for (int i = 0; i < 32; i += 8) {
        float v = t[x][y+i];
        size_t o = (size_t)(c0 + y + i)*R + r0 + x;
        __nv_bfloat16 h, l; split2(v, h, l);
        dH[o] = h; dL[o] = l;
    }
}

// ---------------- xpos tables ----------------
__global__ void xpos_tables_k() {
    int idx = blockIdx.x * blockDim.x + threadIdx.x;
    if (idx >= Sq*64) return;
    int pos = idx >> 6, i = idx & 63;
    float sv    = (2.0f*i + 0.4f*DKq) / (1.4f*DKq);
    float scale = powf(sv, (float)pos / 512.0f);
    float invf  = powf(10000.0f, -((float)i) / 64.0f);
    float ang   = (float)pos * invf;
    float s, c; sincosf(ang, &s, &c);
    g_cq[idx] = c*scale;  g_sq[idx] = s*scale;
    g_ck[idx] = c/scale;  g_sk[idx] = s/scale;
}

// ---------------- layernorm (rows of 1024) -> hi/lo bf16 ----------------
__global__ __launch_bounds__(256) void layernorm_split_k(const float* __restrict__ x,
                                                         const float* __restrict__ w,
                                                         const float* __restrict__ b,
                                                         __nv_bfloat16* __restrict__ yH,
                                                         __nv_bfloat16* __restrict__ yL) {
    int row = blockIdx.x;
    const float* xr = x + (size_t)row * Dq;
    float v[4]; float s = 0.f;
    #pragma unroll
    for (int i = 0; i < 4; i++) { v[i] = xr[threadIdx.x + i*256]; s += v[i]; }
    __shared__ float red[8];
    #pragma unroll
    for (int o = 16; o > 0; o >>= 1) s += __shfl_xor_sync(~0u, s, o);
    if ((threadIdx.x & 31) == 0) red[threadIdx.x >> 5] = s;
    __syncthreads();
    float mu = 0.f;
    #pragma unroll
    for (int i = 0; i < 8; i++) mu += red[i];
    mu *= (1.0f/Dq);
    __syncthreads();
    float vs = 0.f;
    #pragma unroll
    for (int i = 0; i < 4; i++) { float d = v[i]-mu; vs += d*d; }
    #pragma unroll
    for (int o = 16; o > 0; o >>= 1) vs += __shfl_xor_sync(~0u, vs, o);
    if ((threadIdx.x & 31) == 0) red[threadIdx.x >> 5] = vs;
    __syncthreads();
    float var = 0.f;
    #pragma unroll
    for (int i = 0; i < 8; i++) var += red[i];
    var *= (1.0f/Dq);
    float rstd = rsqrtf(var + EPSq);
    #pragma unroll
    for (int i = 0; i < 4; i++) {
        int c = threadIdx.x + i*256;
        float o = (v[i]-mu)*rstd*w[c] + b[c];
        __nv_bfloat16 h, l; split2(o, h, l);
        yH[(size_t)row*Dq + c] = h;
        yL[(size_t)row*Dq + c] = l;
    }
}

// ---------------- xpos apply + decay fold + hi/lo split ----------------
// Q row scaled by gamma^(s&63), K row scaled by gamma^(-(s&63))
__global__ void xpos_apply_k() {
    int idx = blockIdx.x * blockDim.x + threadIdx.x;
    if (idx >= Bq*Sq*Hq*64) return;
    int i = idx & 63, h = (idx >> 6) & 7, s = (idx >> 9) & (Sq-1), b = idx >> 20;
    int row = b*Sq + s;
    const float* qr = g_QKVG + (size_t)row * NCAT;
    int ti = s*64 + i;
    size_t ob = ((size_t)(b*Hq + h)*Sq + s)*DKq + 2*i;

    double lg = log(1.0/32.0) + (double)h * ((log(1.0/512.0) - log(1.0/32.0)) / 7.0);
    float gamma = 1.0f - (float)exp(lg);
    float l2g = log2f(gamma);
    int nl = s & 63;
    float qsc = exp2f((float)nl * l2g);     // <= 1
    float ksc = exp2f(-(float)nl * l2g);    // <= gamma^-63 ~ 7.4

    {
        float q0 = qr[h*128 + 2*i], q1 = qr[h*128 + 2*i + 1];
        float c = g_cq[ti], sn = g_sq[ti];
        float r0 = (q0*c - q1*sn) * qsc;
        float r1 = (q1*c + q0*sn) * qsc;
        __nv_bfloat16 h0, l0, h1, l1;
        split2(r0, h0, l0); split2(r1, h1, l1);
        g_QrH[ob] = h0; g_QrH[ob+1] = h1;
        g_QrL[ob] = l0; g_QrL[ob+1] = l1;
    }
    {
        float k0 = qr[1024 + h*128 + 2*i], k1 = qr[1024 + h*128 + 2*i + 1];
        float c = g_ck[ti], sn = g_sk[ti];
        float r0 = (k0*c - k1*sn) * ksc;
        float r1 = (k1*c + k0*sn) * ksc;
        __nv_bfloat16 h0, l0, h1, l1;
        split2(r0, h0, l0); split2(r1, h1, l1);
        g_KrH[ob] = h0; g_KrH[ob+1] = h1;
        g_KrL[ob] = l0; g_KrL[ob+1] = l1;
    }
}

// ---------------- V split: QKVG V-part -> (b,h,s,v) hi/lo bf16 ----------------
__global__ void vsplit_k() {
    int idx = blockIdx.x * blockDim.x + threadIdx.x;
    if (idx >= Bq*Sq*VDq/2) return;
    int e2 = idx * 2;
    int v = e2 & (VDq-1);
    int row = e2 >> 11;                   // b*Sq + s
    int h = v >> 8, vv = v & 255;
    const float* src = g_QKVG + (size_t)row*NCAT + 2048 + v;
    int b = row >> 11, s = row & (Sq-1);
    size_t ob = ((size_t)(b*Hq + h)*Sq + s)*DVq + vv;
    float a0 = src[0], a1 = src[1];
    __nv_bfloat16 h0, l0, h1, l1;
    split2(a0, h0, l0); split2(a1, h1, l1);
    *(__nv_bfloat162*)(g_VrH + ob) = __nv_bfloat162(h0, h1);
    *(__nv_bfloat162*)(g_VrL + ob) = __nv_bfloat162(l0, l1);
}

// shared layout strides
#define RSTRQ 272   // (128+8) bf16 * 2B
#define RSTRV 528   // (256+8) bf16 * 2B
#define RSTRS 144   // (64+8)  bf16 * 2B

// =====================================================================
// chunk_kv_k: A_c[k][v] = sum_t K'[t][k] V[t][v]  per (b,h,chunk)
// K' already scaled gamma^(-t mod 64). 128x256 fp32 out.
// =====================================================================
#define KA_KH 0
#define KA_KL 17408
#define KA_VH 34816
#define KA_VL 68608
#define KA_SMEM 102400

__global__ __launch_bounds__(256) void chunk_kv_k() {
    extern __shared__ char smc[];
    const uint32_t sb = s2u(smc);
    const int tid = threadIdx.x, lane = tid & 31, warp = tid >> 5;
    const int c = blockIdx.x, h = blockIdx.y, b = blockIdx.z;
    const size_t bh = (size_t)(b*Hq + h);
    const int t0g = c * 64;

    // load K (64x128) and V (64x256) hi/lo
    {
        int row = tid >> 2, q4 = tid & 3;
        const char* kh = (const char*)(g_KrH + (bh*Sq + t0g)*DKq) + (size_t)row*256;
        const char* kl = (const char*)(g_KrL + (bh*Sq + t0g)*DKq) + (size_t)row*256;
        #pragma unroll
        for (int cc = q4; cc < 16; cc += 4) {
            CP_ASYNC16(sb + KA_KH + row*RSTRQ + cc*16, kh + cc*16);
            CP_ASYNC16(sb + KA_KL + row*RSTRQ + cc*16, kl + cc*16);
        }
        const char* vh = (const char*)(g_VrH + (bh*Sq + t0g)*DVq) + (size_t)row*512;
        const char* vl = (const char*)(g_VrL + (bh*Sq + t0g)*DVq) + (size_t)row*512;
        #pragma unroll
        for (int cc = q4; cc < 32; cc += 4) {
            CP_ASYNC16(sb + KA_VH + row*RSTRV + cc*16, vh + cc*16);
            CP_ASYNC16(sb + KA_VL + row*RSTRV + cc*16, vl + cc*16);
        }
    }
    CP_COMMIT();
    CP_WAIT(0);
    __syncthreads();

    const int wm = (warp >> 1) * 32;   // k rows
    const int wn = (warp & 1) * 128;   // v cols
    float acc[2][16][4];
    #pragma unroll
    for (int a = 0; a < 2; a++)
        #pragma unroll
        for (int n = 0; n < 16; n++)
            #pragma unroll
            for (int e = 0; e < 4; e++) acc[a][n][e] = 0.f;

    #pragma unroll
    for (int ks = 0; ks < 4; ks++) {          // t in steps of 16
        // A-frags: K^T (m = k, red = t) via ldmatrix.trans; reorder {r0,r2,r1,r3}
        uint32_t ahf[2][4], alf[2][4];
        #pragma unroll
        for (int mi = 0; mi < 2; mi++) {
            uint32_t off = (uint32_t)(ks*16 + (lane & 15))*RSTRQ
                         + (uint32_t)(wm + mi*16 + ((lane >> 4) << 3))*2;
            uint32_t r[4];
            LDSM4T(r, sb + KA_KH + off);
            ahf[mi][0] = r[0]; ahf[mi][1] = r[2]; ahf[mi][2] = r[1]; ahf[mi][3] = r[3];
            LDSM4T(r, sb + KA_KL + off);
            alf[mi][0] = r[0]; alf[mi][1] = r[2]; alf[mi][2] = r[1]; alf[mi][3] = r[3];
        }
        #pragma unroll
        for (int vh2 = 0; vh2 < 2; vh2++) {    // v halves of 64
            uint32_t bvh[4][4], bvl[4][4];
            #pragma unroll
            for (int g = 0; g < 4; g++) {
                uint32_t off = (uint32_t)(ks*16 + (lane & 15))*RSTRV
                             + (uint32_t)(wn + vh2*64 + g*16 + ((lane >> 4) << 3))*2;
                LDSM4T(bvh[g], sb + KA_VH + off);
                LDSM4T(bvl[g], sb + KA_VL + off);
            }
            #pragma unroll
            for (int mi = 0; mi < 2; mi++) {
                #pragma unroll
                for (int ni = 0; ni < 8; ni++) {
                    uint32_t b0h = bvh[ni >> 1][(ni & 1)*2], b1h = bvh[ni >> 1][(ni & 1)*2 + 1];
                    uint32_t b0l = bvl[ni >> 1][(ni & 1)*2], b1l = bvl[ni >> 1][(ni & 1)*2 + 1];
                    float* d = acc[mi][vh2*8 + ni];
                    MMA16816(d, ahf[mi], b0h, b1h);
                    MMA16816(d, ahf[mi], b0l, b1l);
                    MMA16816(d, alf[mi], b0h, b1h);
                }
            }
        }
    }

    // write A_c fp32: [bh][c][k][v]
    float* dst = g_A + ((bh*NCH + c) * (size_t)DKq) * DVq;
    #pragma unroll
    for (int mi = 0; mi < 2; mi++) {
        #pragma unroll
        for (int half = 0; half < 2; half++) {
            int r = wm + mi*16 + (lane >> 2) + half*8;
            #pragma unroll
            for (int ni = 0; ni < 16; ni++) {
                int cc = wn + ni*8 + (lane & 3)*2;
                *(float2*)(dst + (size_t)r*DVq + cc) =
                    make_float2(acc[mi][ni][half*2], acc[mi][ni][half*2 + 1]);
            }
        }
    }
}

// =====================================================================
// scan_k: P_c = gamma^64 * (P_{c-1} + A_c); P output split hi/lo bf16.
// one thread per (bh, k, v-pair)
// =====================================================================
__global__ void scan_k() {
    int idx = blockIdx.x * blockDim.x + threadIdx.x;
    if (idx >= Bq*Hq*DKq*(DVq/2)) return;
    int vp = idx & 127;
    int k  = (idx >> 7) & 127;
    int bh = idx >> 14;
    int h = bh & 7;
    double lg = log(1.0/32.0) + (double)h * ((log(1.0/512.0) - log(1.0/32.0)) / 7.0);
    float gamma = 1.0f - (float)exp(lg);
    float g64 = exp2f(64.0f * log2f(gamma));
    size_t base = ((size_t)bh*NCH*DKq + k)*DVq + vp*2;
    const size_t cstr = (size_t)DKq*DVq;
    float p0 = 0.f, p1 = 0.f;
    for (int c = 0; c < NCH; c++) {
        float2 a = *(const float2*)(g_A + base + c*cstr);
        p0 = (p0 + a.x) * g64;
        p1 = (p1 + a.y) * g64;
        __nv_bfloat16 h0, l0, h1, l1;
        split2(p0, h0, l0); split2(p1, h1, l1);
        *(__nv_bfloat162*)(g_PH + base + c*cstr) = __nv_bfloat162(h0, h1);
        *(__nv_bfloat162*)(g_PL + base + c*cstr) = __nv_bfloat162(l0, l1);
    }
}

// =====================================================================
// chunk_apply_k: per (b,h,chunk c):
//   Y = intra-chunk retention (diag tile) + Q' * P_{c-1}
// =====================================================================
#define C_QH 0
#define C_QL 17408
#define C_KH 34816
#define C_KL 52224
#define C_VH 69632
#define C_VL 103424
#define C_SH 137216
#define C_SL 146432
#define C_PB 155648         // + buf*33792; lo at +16896
#define KC_SMEM 223232

__global__ __launch_bounds__(256) void chunk_apply_k() {
    extern __shared__ char smc[];
    const uint32_t sb = s2u(smc);
    const int tid = threadIdx.x, lane = tid & 31, warp = tid >> 5;
    const int c = blockIdx.x, h = blockIdx.y, b = blockIdx.z;
    const size_t bh = (size_t)(b*Hq + h);
    const int s0 = c * 64;

    // ---- issue loads: Q,K,V (group 0), then P quarters 0,1 (groups 1,2) ----
    {
        int row = tid >> 2, q4 = tid & 3;
        const char* qh = (const char*)(g_QrH + (bh*Sq + s0)*DKq) + (size_t)row*256;
        const char* ql = (const char*)(g_QrL + (bh*Sq + s0)*DKq) + (size_t)row*256;
        const char* kh = (const char*)(g_KrH + (bh*Sq + s0)*DKq) + (size_t)row*256;
        const char* kl = (const char*)(g_KrL + (bh*Sq + s0)*DKq) + (size_t)row*256;
        #pragma unroll
        for (int cc = q4; cc < 16; cc += 4) {
            CP_ASYNC16(sb + C_QH + row*RSTRQ + cc*16, qh + cc*16);
            CP_ASYNC16(sb + C_QL + row*RSTRQ + cc*16, ql + cc*16);
            CP_ASYNC16(sb + C_KH + row*RSTRQ + cc*16, kh + cc*16);
            CP_ASYNC16(sb + C_KL + row*RSTRQ + cc*16, kl + cc*16);
        }
        const char* vh = (const char*)(g_VrH + (bh*Sq + s0)*DVq) + (size_t)row*512;
        const char* vl = (const char*)(g_VrL + (bh*Sq + s0)*DVq) + (size_t)row*512;
        #pragma unroll
        for (int cc = q4; cc < 32; cc += 4) {
            CP_ASYNC16(sb + C_VH + row*RSTRV + cc*16, vh + cc*16);
            CP_ASYNC16(sb + C_VL + row*RSTRV + cc*16, vl + cc*16);
        }
    }
    CP_COMMIT();

    const int prow = tid >> 3, pc8 = tid & 7;
    const char* PHrowbase = (const char*)(g_PH + ((bh*NCH + (c-1))*(size_t)DKq)*DVq);
    const char* PLrowbase = (const char*)(g_PL + ((bh*NCH + (c-1))*(size_t)DKq)*DVq);

    if (c > 0) {
        #pragma unroll
        for (int q = 0; q < 2; q++) {
            uint32_t bufb = C_PB + q*33792;
            const char* ph = PHrowbase + (size_t)(q*32 + prow)*512;
            const char* pl = PLrowbase + (size_t)(q*32 + prow)*512;
            #pragma unroll
            for (int cc = pc8; cc < 32; cc += 8) {
                CP_ASYNC16(sb + bufb + prow*RSTRV + cc*16, ph + cc*16);
                CP_ASYNC16(sb + bufb + 16896 + prow*RSTRV + cc*16, pl + cc*16);
            }
            CP_COMMIT();
        }
        CP_WAIT(2);    // QKV arrived
    } else {
        CP_WAIT(0);
    }
    __syncthreads();

    const int wm  = (warp >> 2) * 32;
    const int wn1 = (warp & 3) * 16;
    const int wn2 = (warp & 3) * 64;

    float accY[2][8][4];
    #pragma unroll
    for (int a = 0; a < 2; a++)
        #pragma unroll
        for (int n = 0; n < 8; n++)
            #pragma unroll
            for (int e = 0; e < 4; e++) accY[a][n][e] = 0.f;

    // ---- intra phase 1: S = Q K^T (3 terms), causal mask, split to smem ----
    {
        float sc[2][2][4];
        #pragma unroll
        for (int a = 0; a < 2; a++)
            #pragma unroll
            for (int n = 0; n < 2; n++)
                #pragma unroll
                for (int e = 0; e < 4; e++) sc[a][n][e] = 0.f;

        #pragma unroll
        for (int ks = 0; ks < 8; ks++) {
            uint32_t ah[2][4], al[2][4];
            #pragma unroll
            for (int mi = 0; mi < 2; mi++) {
                uint32_t off = (uint32_t)(wm + mi*16 + (lane & 15))*RSTRQ
                             + (uint32_t)(ks*16 + ((lane >> 4) << 3))*2;
                LDSM4(ah[mi], sb + C_QH + off);
                LDSM4(al[mi], sb + C_QL + off);
            }
            uint32_t bh4[4], bl4[4];
            {
                uint32_t off = (uint32_t)(wn1 + ((lane >> 4) << 3) + (lane & 7))*RSTRQ
                             + (uint32_t)(ks*16 + (((lane >> 3) & 1) << 3))*2;
                LDSM4(bh4, sb + C_KH + off);
                LDSM4(bl4, sb + C_KL + off);
            }
            #pragma unroll
            for (int mi = 0; mi < 2; mi++) {
                #pragma unroll
                for (int ni = 0; ni < 2; ni++) {
                    uint32_t b0h = bh4[ni*2], b1h = bh4[ni*2+1];
                    uint32_t b0l = bl4[ni*2], b1l = bl4[ni*2+1];
                    MMA16816(sc[mi][ni], ah[mi], b0h, b1h);
                    MMA16816(sc[mi][ni], ah[mi], b0l, b1l);
                    MMA16816(sc[mi][ni], al[mi], b0h, b1h);
                }
            }
        }
        #pragma unroll
        for (int mi = 0; mi < 2; mi++) {
            #pragma unroll
            for (int half = 0; half < 2; half++) {
                int n_l = wm + mi*16 + (lane >> 2) + half*8;
                #pragma unroll
                for (int ni = 0; ni < 2; ni++) {
                    int m_l = wn1 + ni*8 + (lane & 3)*2;
                    float v0 = sc[mi][ni][half*2];
                    float v1 = sc[mi][ni][half*2 + 1];
                    if (n_l < m_l)     v0 = 0.f;
                    if (n_l < m_l + 1) v1 = 0.f;
                    __nv_bfloat16 h0, l0, h1, l1;
                    split2(v0, h0, l0); split2(v1, h1, l1);
                    uint32_t off = (uint32_t)n_l*RSTRS + (uint32_t)m_l*2;
                    *(__nv_bfloat162*)(smc + C_SH + off) = __nv_bfloat162(h0, h1);
                    *(__nv_bfloat162*)(smc + C_SL + off) = __nv_bfloat162(l0, l1);
                }
            }
        }
    }
    __syncthreads();

    // ---- intra phase 2: Y += S V (3 terms), V via ldmatrix.trans ----
    #pragma unroll
    for (int ks = 0; ks < 4; ks++) {
        uint32_t ah[2][4], al[2][4];
        #pragma unroll
        for (int mi = 0; mi < 2; mi++) {
            uint32_t off = (uint32_t)(wm + mi*16 + (lane & 15))*RSTRS
                         + (uint32_t)(ks*16 + ((lane >> 4) << 3))*2;
            LDSM4(ah[mi], sb + C_SH + off);
            LDSM4(al[mi], sb + C_SL + off);
        }
        uint32_t bvh[4][4], bvl[4][4];
        #pragma unroll
        for (int g = 0; g < 4; g++) {
            uint32_t off = (uint32_t)(ks*16 + (lane & 15))*RSTRV
                         + (uint32_t)(wn2 + g*16 + ((lane >> 4) << 3))*2;
            LDSM4T(bvh[g], sb + C_VH + off);
            LDSM4T(bvl[g], sb + C_VL + off);
        }
        #pragma unroll
        for (int mi = 0; mi < 2; mi++) {
            #pragma unroll
            for (int ni = 0; ni < 8; ni++) {
                uint32_t b0h = bvh[ni >> 1][(ni & 1)*2], b1h = bvh[ni >> 1][(ni & 1)*2 + 1];
                uint32_t b0l = bvl[ni >> 1][(ni & 1)*2], b1l = bvl[ni >> 1][(ni & 1)*2 + 1];
                MMA16816(accY[mi][ni], ah[mi], b0h, b1h);
                MMA16816(accY[mi][ni], ah[mi], b0l, b1l);
                MMA16816(accY[mi][ni], al[mi], b0h, b1h);
            }
        }
    }

    // ---- inter: Y += Q' * P_{c-1}, reduced over k=128 in 4 quarters ----
    if (c > 0) {
        #pragma unroll
        for (int q = 0; q < 4; q++) {
            if (q < 3) { CP_WAIT(1); } else { CP_WAIT(0); }
            __syncthreads();
            const uint32_t bufb = C_PB + (q & 1)*33792;
            #pragma unroll
            for (int ks = 0; ks < 2; ks++) {
                uint32_t ah[2][4], al[2][4];
                #pragma unroll
                for (int mi = 0; mi < 2; mi++) {
                    uint32_t off = (uint32_t)(wm + mi*16 + (lane & 15))*RSTRQ
                                 + (uint32_t)(q*32 + ks*16 + ((lane >> 4) << 3))*2;
                    LDSM4(ah[mi], sb + C_QH + off);
                    LDSM4(al[mi], sb + C_QL + off);
                }
                uint32_t bvh[4][4], bvl[4][4];
                #pragma unroll
                for (int g = 0; g < 4; g++) {
                    uint32_t off = (uint32_t)(ks*16 + (lane & 15))*RSTRV
                                 + (uint32_t)(wn2 + g*16 + ((lane >> 4) << 3))*2;
                    LDSM4T(bvh[g], sb + bufb + off);
                    LDSM4T(bvl[g], sb + bufb + 16896 + off);
                }
                #pragma unroll
                for (int mi = 0; mi < 2; mi++) {
                    #pragma unroll
                    for (int ni = 0; ni < 8; ni++) {
                        uint32_t b0h = bvh[ni >> 1][(ni & 1)*2], b1h = bvh[ni >> 1][(ni & 1)*2 + 1];
                        uint32_t b0l = bvl[ni >> 1][(ni & 1)*2], b1l = bvl[ni >> 1][(ni & 1)*2 + 1];
                        MMA16816(accY[mi][ni], ah[mi], b0h, b1h);
                        MMA16816(accY[mi][ni], ah[mi], b0l, b1l);
                        MMA16816(accY[mi][ni], al[mi], b0h, b1h);
                    }
                }
            }
            if (q < 2) {
                __syncthreads();
                uint32_t nb = C_PB + (q & 1)*33792;
                const char* ph = PHrowbase + (size_t)((q+2)*32 + prow)*512;
                const char* pl = PLrowbase + (size_t)((q+2)*32 + prow)*512;
                #pragma unroll
                for (int cc = pc8; cc < 32; cc += 8) {
                    CP_ASYNC16(sb + nb + prow*RSTRV + cc*16, ph + cc*16);
                    CP_ASYNC16(sb + nb + 16896 + prow*RSTRV + cc*16, pl + cc*16);
                }
                CP_COMMIT();
            }
        }
    }

    // write Y: (b, s, h*DV + vd)
    #pragma unroll
    for (int mi = 0; mi < 2; mi++) {
        #pragma unroll
        for (int half = 0; half < 2; half++) {
            int r = s0 + wm + mi*16 + (lane >> 2) + half*8;
            float* yr = g_Y + (size_t)(b*Sq + r)*VDq + h*DVq;
            #pragma unroll
            for (int ni = 0; ni < 8; ni++) {
                int cc = wn2 + ni*8 + (lane & 3)*2;
                *(float2*)(yr + cc) = make_float2(accY[mi][ni][half*2], accY[mi][ni][half*2 + 1]);
            }
        }
    }
}

// ---------------- groupnorm + SiLU gate -> hi/lo bf16 ----------------
__global__ __launch_bounds__(256) void gn_gate_k(const float* __restrict__ gn_w,
                                                 const float* __restrict__ gn_b) {
    int row  = blockIdx.x;
    int head = threadIdx.x >> 5;
    int lane = threadIdx.x & 31;
    const float* Yr = g_Y + (size_t)row*VDq + head*DVq;
    float v[8]; float s = 0.f;
    #pragma unroll
    for (int i = 0; i < 8; i++) { v[i] = Yr[lane + i*32]; s += v[i]; }
    #pragma unroll
    for (int o = 16; o > 0; o >>= 1) s += __shfl_xor_sync(~0u, s, o);
    float mu = s * (1.0f/DVq);
    float vs = 0.f;
    #pragma unroll
    for (int i = 0; i < 8; i++) { float d = v[i]-mu; vs += d*d; }
    #pragma unroll
    for (int o = 16; o > 0; o >>= 1) vs += __shfl_xor_sync(~0u, vs, o);
    float rstd = rsqrtf(vs * (1.0f/DVq) + EPSq);
    const float* Gr = g_QKVG + (size_t)row*NCAT + 4096 + head*DVq;
    #pragma unroll
    for (int i = 0; i < 8; i++) {
        int c = head*DVq + lane + i*32;
        float y = (v[i]-mu)*rstd*gn_w[c] + gn_b[c];
        float g = Gr[lane + i*32];
        float sg = g / (1.0f + expf(-g));
        float o = sg * y;
        __nv_bfloat16 h, l; split2(o, h, l);
        g_YH[(size_t)row*VDq + c] = h;
        g_YL[(size_t)row*VDq + c] = l;
    }
}

// =====================================================================
// HMMA bf16-split GEMM (unchanged, proven)
// =====================================================================
#define LDT 40
#define MAT_ELE (128*LDT)
#define STG_BYTES (4*MAT_ELE*2)
#define GT_SMEM (2*STG_BYTES)

template<int EPI>
__global__ __launch_bounds__(256) void tgemm_k(
    const __nv_bfloat16* __restrict__ Ah, const __nv_bfloat16* __restrict__ Al,
    const __nv_bfloat16* __restrict__ Bh, const __nv_bfloat16* __restrict__ Bl,
    float* __restrict__ C,
    __nv_bfloat16* __restrict__ CH, __nv_bfloat16* __restrict__ CL,
    int M, int N, int K,
    const float* __restrict__ bias, const float* __restrict__ res)
{
    extern __shared__ __nv_bfloat16 smg[];
    const uint32_t sbase = s2u(smg);
    const int tid = threadIdx.x, lane = tid & 31, warp = tid >> 5;
    const int row0 = blockIdx.y * 128, col0 = blockIdx.x * 128;
    const int wm = (warp >> 2) * 64, wn = (warp & 3) * 32;

    const int r_ = tid >> 2, q_ = tid & 3;

    float acc[4][4][4];
    #pragma unroll
    for (int a = 0; a < 4; a++)
        #pragma unroll
        for (int b = 0; b < 4; b++)
            #pragma unroll
            for (int c = 0; c < 4; c++) acc[a][b][c] = 0.f;

    const int nch = K >> 5;

    auto load_stage = [&](int stage, int k0) {
        const uint32_t sb = sbase + (uint32_t)stage * STG_BYTES;
        #pragma unroll
        for (int mat = 0; mat < 4; mat++) {
            const __nv_bfloat16* base = (mat == 0) ? Ah : (mat == 1) ? Al : (mat == 2) ? Bh : Bl;
            const int grow0 = (mat < 2) ? row0 : col0;
            #pragma unroll
            for (int h = 0; h < 2; h++) {
                int row = r_ + h*64;
                const __nv_bfloat16* src = base + (size_t)(grow0 + row) * K + k0 + q_*8;
                uint32_t dst = sb + (uint32_t)(mat*MAT_ELE + row*LDT + q_*8) * 2;
                CP_ASYNC16(dst, src);
            }
        }
    };

    load_stage(0, 0);
    CP_COMMIT();

    for (int ch = 0; ch < nch; ch++) {
        if (ch + 1 < nch) {
            load_stage((ch + 1) & 1, (ch + 1) << 5);
            CP_COMMIT();
            CP_WAIT(1);
        } else {
            CP_WAIT(0);
        }
        __syncthreads();

        const uint32_t sb = sbase + (uint32_t)(ch & 1) * STG_BYTES;
        const uint32_t aHb = sb, aLb = sb + MAT_ELE*2;
        const uint32_t bHb = sb + 2*MAT_ELE*2, bLb = sb + 3*MAT_ELE*2;

        #pragma unroll
        for (int ks = 0; ks < 2; ks++) {
            uint32_t ah[4][4], al[4][4];
            #pragma unroll
            for (int mi = 0; mi < 4; mi++) {
                uint32_t off = (uint32_t)((wm + mi*16 + (lane & 15))*LDT + ks*16 + ((lane >> 4) << 3)) * 2;
                LDSM4(ah[mi], aHb + off);
                LDSM4(al[mi], aLb + off);
            }
            uint32_t bh[2][4], bl[2][4];
            #pragma unroll
            for (int gi = 0; gi < 2; gi++) {
                uint32_t off = (uint32_t)((wn + gi*16 + ((lane >> 4) << 3) + (lane & 7))*LDT
                                          + ks*16 + (((lane >> 3) & 1) << 3)) * 2;
                LDSM4(bh[gi], bHb + off);
                LDSM4(bl[gi], bLb + off);
            }
            #pragma unroll
            for (int mi = 0; mi < 4; mi++) {
                #pragma unroll
                for (int ni = 0; ni < 4; ni++) {
                    uint32_t b0h = bh[ni >> 1][(ni & 1)*2], b1h = bh[ni >> 1][(ni & 1)*2 + 1];
                    uint32_t b0l = bl[ni >> 1][(ni & 1)*2], b1l = bl[ni >> 1][(ni & 1)*2 + 1];
                    MMA16816(acc[mi][ni], ah[mi], b0h, b1h);
                    MMA16816(acc[mi][ni], ah[mi], b0l, b1l);
                    MMA16816(acc[mi][ni], al[mi], b0h, b1h);
                }
            }
        }
        __syncthreads();
    }

    const int rb = row0 + wm + (lane >> 2);
    const int cb = col0 + wn + (lane & 3)*2;
    #pragma unroll
    for (int mi = 0; mi < 4; mi++) {
        #pragma unroll
        for (int half = 0; half < 2; half++) {
            size_t r = (size_t)(rb + mi*16 + half*8);
            #pragma unroll
            for (int ni = 0; ni < 4; ni++) {
                int c = cb + ni*8;
                float v0 = acc[mi][ni][half*2 + 0];
                float v1 = acc[mi][ni][half*2 + 1];
                if (EPI == 1) {
                    v0 += bias[c];   v0 = 0.5f*v0*(1.0f + erff(v0*0.70710678118654752f));
                    v1 += bias[c+1]; v1 = 0.5f*v1*(1.0f + erff(v1*0.70710678118654752f));
                    __nv_bfloat16 h0, l0, h1, l1;
                    split2(v0, h0, l0); split2(v1, h1, l1);
                    *(__nv_bfloat162*)(CH + r*N + c) = __nv_bfloat162(h0, h1);
                    *(__nv_bfloat162*)(CL + r*N + c) = __nv_bfloat162(l0, l1);
                } else {
                    if (EPI == 2) { v0 += bias[c] + res[r*N + c]; v1 += bias[c+1] + res[r*N + c + 1]; }
                    else if (EPI == 3) { v0 += res[r*N + c]; v1 += res[r*N + c + 1]; }
                    *(float2*)(C + r*N + c) = make_float2(v0, v1);
                }
            }
        }
    }
}

// ---------------- launcher ----------------
extern "C" void kernel_launch(void* const* d_in, const int* in_sizes, int n_in,
                              void* d_out, int out_size) {
    const float* X      = (const float*)d_in[0];
    const float* Wq     = (const float*)d_in[1];
    const float* Wk     = (const float*)d_in[2];
    const float* Wv     = (const float*)d_in[3];
    const float* W_G    = (const float*)d_in[4];
    const float* W_O    = (const float*)d_in[5];
    const float* gn_w   = (const float*)d_in[6];
    const float* gn_b   = (const float*)d_in[7];
    const float* ln1_w  = (const float*)d_in[8];
    const float* ln1_b  = (const float*)d_in[9];
    const float* ln2_w  = (const float*)d_in[10];
    const float* ln2_b  = (const float*)d_in[11];
    const float* ffn_w1 = (const float*)d_in[12];
    const float* ffn_b1 = (const float*)d_in[13];
    const float* ffn_w2 = (const float*)d_in[14];
    const float* ffn_b2 = (const float*)d_in[15];
    float* out = (float*)d_out;

    float* p_Wcat;  cudaGetSymbolAddress((void**)&p_Wcat,  g_Wcat);
    float* p_QKVG;  cudaGetSymbolAddress((void**)&p_QKVG,  g_QKVG);
    float* p_X2;    cudaGetSymbolAddress((void**)&p_X2,    g_X2);
    __nv_bfloat16 *p_XnH, *p_XnL, *p_WcTH, *p_WcTL, *p_WOTH, *p_WOTL;
    __nv_bfloat16 *p_W1TH, *p_W1TL, *p_W2TH, *p_W2TL, *p_YH, *p_YL;
    __nv_bfloat16 *p_HnH, *p_HnL, *p_FfH, *p_FfL;
    cudaGetSymbolAddress((void**)&p_XnH,  g_XnH);  cudaGetSymbolAddress((void**)&p_XnL,  g_XnL);
    cudaGetSymbolAddress((void**)&p_WcTH, g_WcTH); cudaGetSymbolAddress((void**)&p_WcTL, g_WcTL);
    cudaGetSymbolAddress((void**)&p_WOTH, g_WOTH); cudaGetSymbolAddress((void**)&p_WOTL, g_WOTL);
    cudaGetSymbolAddress((void**)&p_W1TH, g_W1TH); cudaGetSymbolAddress((void**)&p_W1TL, g_W1TL);
    cudaGetSymbolAddress((void**)&p_W2TH, g_W2TH); cudaGetSymbolAddress((void**)&p_W2TL, g_W2TL);
    cudaGetSymbolAddress((void**)&p_YH,   g_YH);   cudaGetSymbolAddress((void**)&p_YL,   g_YL);
    cudaGetSymbolAddress((void**)&p_HnH,  g_HnH);  cudaGetSymbolAddress((void**)&p_HnL,  g_HnL);
    cudaGetSymbolAddress((void**)&p_FfH,  g_FfH);  cudaGetSymbolAddress((void**)&p_FfL,  g_FfL);

    cudaFuncSetAttribute(tgemm_k<0>, cudaFuncAttributeMaxDynamicSharedMemorySize, GT_SMEM);
    cudaFuncSetAttribute(tgemm_k<1>, cudaFuncAttributeMaxDynamicSharedMemorySize, GT_SMEM);
    cudaFuncSetAttribute(tgemm_k<2>, cudaFuncAttributeMaxDynamicSharedMemorySize, GT_SMEM);
    cudaFuncSetAttribute(tgemm_k<3>, cudaFuncAttributeMaxDynamicSharedMemorySize, GT_SMEM);
    cudaFuncSetAttribute(chunk_kv_k,    cudaFuncAttributeMaxDynamicSharedMemorySize, KA_SMEM);
    cudaFuncSetAttribute(chunk_apply_k, cudaFuncAttributeMaxDynamicSharedMemorySize, KC_SMEM);

    // launch order arranged so the 6th launch (ncu -s 5 -c 1) is the QKVG GEMM
    repack_k<<<(Dq*NCAT + 255)/256, 256>>>(Wq, Wk, Wv, W_G);                       // 1
    xpos_tables_k<<<(Sq*64 + 255)/256, 256>>>();                                   // 2
    transpose_split_k<<<dim3(NCAT/32, Dq/32), 256>>>(p_Wcat, p_WcTH, p_WcTL, Dq, NCAT); // 3
    transpose_split_k<<<dim3(Dq/32, VDq/32), 256>>>(W_O,    p_WOTH, p_WOTL, VDq, Dq);   // 4
    layernorm_split_k<<<Mq, 256>>>(X, ln1_w, ln1_b, p_XnH, p_XnL);                 // 5
    tgemm_k<0><<<dim3(NCAT/128, Mq/128), 256, GT_SMEM>>>(                          // 6  <- profiled
        p_XnH, p_XnL, p_WcTH, p_WcTL, p_QKVG, nullptr, nullptr, Mq, NCAT, Dq, nullptr, nullptr);
    transpose_split_k<<<dim3(FFNq/32, Dq/32), 256>>>(ffn_w1, p_W1TH, p_W1TL, Dq, FFNq); // 7
    transpose_split_k<<<dim3(Dq/32, FFNq/32), 256>>>(ffn_w2, p_W2TH, p_W2TL, FFNq, Dq); // 8

    // rotary + decay fold + split; V split
    xpos_apply_k<<<(Bq*Sq*Hq*64 + 255)/256, 256>>>();
    vsplit_k<<<(Bq*Sq*VDq/2 + 255)/256, 256>>>();

    // chunked linear retention
    chunk_kv_k<<<dim3(NCH, Hq, Bq), 256, KA_SMEM>>>();
    scan_k<<<(Bq*Hq*DKq*(DVq/2) + 255)/256, 256>>>();
    chunk_apply_k<<<dim3(NCH, Hq, Bq), 256, KC_SMEM>>>();

    // groupnorm + gate -> hi/lo
    gn_gate_k<<<Mq, 256>>>(gn_w, gn_b);

    // output projection + residual -> X2 (fp32)
    tgemm_k<3><<<dim3(Dq/128, Mq/128), 256, GT_SMEM>>>(
        p_YH, p_YL, p_WOTH, p_WOTL, p_X2, nullptr, nullptr, Mq, Dq, VDq, nullptr, X);

    // LN2 -> hi/lo
    layernorm_split_k<<<Mq, 256>>>(p_X2, ln2_w, ln2_b, p_HnH, p_HnL);

    // FFN1 + gelu -> hi/lo
    tgemm_k<1><<<dim3(FFNq/128, Mq/128), 256, GT_SMEM>>>(
        p_HnH, p_HnL, p_W1TH, p_W1TL, nullptr, p_FfH, p_FfL, Mq, FFNq, Dq, ffn_b1, nullptr);

    // FFN2 + bias + residual -> out
    tgemm_k<2><<<dim3(Dq/128, Mq/128), 256, GT_SMEM>>>(
        p_FfH, p_FfL, p_W2TH, p_W2TL, out, nullptr, nullptr, Mq, Dq, FFNq, ffn_b2, p_X2);

    (void)in_sizes; (void)n_in; (void)out_size;
}